// round 1
// baseline (speedup 1.0000x reference)
#include <cuda_runtime.h>

#define N_NODES 60000
#define N_HERB  5000
#define NOUT2   25000     // herbs + proteins: only layer-2 rows we ever need
#define DIM     128
#define NREL    6
#define NB      30
#define NE      600000
#define NP      40000
#define K1      896       // 6*128 (relations) + 128 (root)
#define YSTRIDE 896

// ---------------- scratch (static device allocations; no cudaMalloc) ----------------
__device__ float g_B1[DIM * K1];                       // B for GEMM1: [d][r*128+o | 768+o]
__device__ float g_B2[K1 * DIM];                       // B for GEMM2: [r*128+d | 768+d][o]
__device__ float g_y [(size_t)N_NODES * YSTRIDE];      // layer-1: messages (cols 0:768) + out accum (768:896)
__device__ float g_x1[(size_t)N_NODES * DIM];          // relu(layer1)
__device__ float g_agg2[(size_t)NOUT2 * NREL * DIM];   // layer-2 per-(dst,rel) sums
__device__ float g_x2[(size_t)NOUT2 * DIM];            // layer-2 output
__device__ int   g_cnt[N_NODES * NREL];
__device__ float g_inv[N_NODES * NREL];

// ---------------- packed f32x2 FMA (B300 2x fp32 path) ----------------
__device__ __forceinline__ void ffma2(unsigned long long &d, unsigned long long a, unsigned long long b) {
    asm volatile("fma.rn.f32x2 %0, %1, %2, %0;" : "+l"(d) : "l"(a), "l"(b));
}
__device__ __forceinline__ unsigned long long pack2(float x) {
    unsigned u = __float_as_uint(x);
    return ((unsigned long long)u << 32) | (unsigned long long)u;
}
__device__ __forceinline__ float lo32(unsigned long long v) { return __uint_as_float((unsigned)(v & 0xffffffffull)); }
__device__ __forceinline__ float hi32(unsigned long long v) { return __uint_as_float((unsigned)(v >> 32)); }

// ---------------- weight build: W_r = sum_b comp[r,b]*basis[b], plus root ----------------
__global__ void k_build_w(const float* __restrict__ basis, const float* __restrict__ comp,
                          const float* __restrict__ root, int layer) {
    int idx = blockIdx.x * blockDim.x + threadIdx.x;
    if (idx < NREL * DIM * DIM) {
        int r = idx / (DIM * DIM);
        int d = (idx / DIM) % DIM;
        int o = idx % DIM;
        float s = 0.f;
        #pragma unroll
        for (int b = 0; b < NB; b++)
            s += comp[r * NB + b] * basis[(size_t)b * DIM * DIM + d * DIM + o];
        if (layer == 0) g_B1[d * K1 + r * DIM + o] = s;
        else            g_B2[(r * DIM + d) * DIM + o] = s;
    } else {
        int j = idx - NREL * DIM * DIM;
        if (j < DIM * DIM) {
            int d = j / DIM, o = j % DIM;
            if (layer == 0) g_B1[d * K1 + NREL * DIM + o] = root[j];
            else            g_B2[(NREL * DIM + d) * DIM + o] = root[j];
        }
    }
}

// ---------------- counts ----------------
__global__ void k_zero_cnt() {
    int i = blockIdx.x * blockDim.x + threadIdx.x;
    if (i < N_NODES * NREL) g_cnt[i] = 0;
}
__global__ void k_count(const int* __restrict__ ei, const int* __restrict__ et) {
    int e = blockIdx.x * blockDim.x + threadIdx.x;
    if (e < NE) {
        int dst = ei[NE + e];
        atomicAdd(&g_cnt[dst * NREL + et[e]], 1);
    }
}
__global__ void k_inv() {
    int i = blockIdx.x * blockDim.x + threadIdx.x;
    if (i < N_NODES * NREL) {
        int c = g_cnt[i];
        g_inv[i] = 1.0f / (float)(c > 0 ? c : 1);
    }
}

// ---------------- GEMM1: y[60000,896] = x[60000,128] @ B1[128,896]  (+bias1 on root cols) ----------------
__global__ __launch_bounds__(256) void k_gemm1(const float* __restrict__ X, const float* __restrict__ bias1) {
    __shared__ float As[8][128];
    __shared__ float Bs[8][128];
    const int row0 = blockIdx.x * 128;
    const int col0 = blockIdx.y * 128;
    const int tid = threadIdx.x;
    const int tx = tid & 15, ty = tid >> 4;
    unsigned long long acc[8][4];
    #pragma unroll
    for (int i = 0; i < 8; i++)
        #pragma unroll
        for (int j = 0; j < 4; j++) acc[i][j] = 0ull;
    const int ar = tid >> 1, ak = (tid & 1) * 4;
    const int bk = tid >> 5, bc = (tid & 31) * 4;
    const int arow = row0 + ar;
    for (int k0 = 0; k0 < DIM; k0 += 8) {
        float4 av = make_float4(0.f, 0.f, 0.f, 0.f);
        if (arow < N_NODES) av = *(const float4*)(X + (size_t)arow * DIM + k0 + ak);
        As[ak + 0][ar] = av.x; As[ak + 1][ar] = av.y; As[ak + 2][ar] = av.z; As[ak + 3][ar] = av.w;
        *(float4*)&Bs[bk][bc] = *(const float4*)(g_B1 + (size_t)(k0 + bk) * K1 + col0 + bc);
        __syncthreads();
        #pragma unroll
        for (int k = 0; k < 8; k++) {
            float4 a0 = *(float4*)&As[k][ty * 8];
            float4 a1 = *(float4*)&As[k][ty * 8 + 4];
            unsigned long long b0 = *(unsigned long long*)&Bs[k][tx * 8 + 0];
            unsigned long long b1 = *(unsigned long long*)&Bs[k][tx * 8 + 2];
            unsigned long long b2 = *(unsigned long long*)&Bs[k][tx * 8 + 4];
            unsigned long long b3 = *(unsigned long long*)&Bs[k][tx * 8 + 6];
            float a8[8] = {a0.x, a0.y, a0.z, a0.w, a1.x, a1.y, a1.z, a1.w};
            #pragma unroll
            for (int i = 0; i < 8; i++) {
                unsigned long long a2 = pack2(a8[i]);
                ffma2(acc[i][0], a2, b0);
                ffma2(acc[i][1], a2, b1);
                ffma2(acc[i][2], a2, b2);
                ffma2(acc[i][3], a2, b3);
            }
        }
        __syncthreads();
    }
    #pragma unroll
    for (int i = 0; i < 8; i++) {
        int r = row0 + ty * 8 + i;
        if (r >= N_NODES) continue;
        #pragma unroll
        for (int j = 0; j < 4; j++) {
            int c = col0 + tx * 8 + j * 2;
            float lo = lo32(acc[i][j]);
            float hi = hi32(acc[i][j]);
            if (c >= NREL * DIM) { lo += bias1[c - NREL * DIM]; hi += bias1[c + 1 - NREL * DIM]; }
            *(float2*)(g_y + (size_t)r * YSTRIDE + c) = make_float2(lo, hi);
        }
    }
}

// ---------------- scatter1: y[dst, 768:896] += y[src, t*128:(t+1)*128] * inv[dst,t] ----------------
__global__ __launch_bounds__(256) void k_scatter1(const int* __restrict__ ei, const int* __restrict__ et) {
    int gw = (int)((blockIdx.x * 256u + threadIdx.x) >> 5);
    if (gw >= NE) return;
    int lane = threadIdx.x & 31;
    int src = ei[gw], dst = ei[NE + gw], t = et[gw];
    float s = g_inv[dst * NREL + t];
    const float4 v = *(const float4*)(g_y + (size_t)src * YSTRIDE + t * DIM + lane * 4);
    float* p = g_y + (size_t)dst * YSTRIDE + NREL * DIM + lane * 4;
    asm volatile("red.global.add.v4.f32 [%0], {%1, %2, %3, %4};"
                 :: "l"(p), "f"(v.x * s), "f"(v.y * s), "f"(v.z * s), "f"(v.w * s) : "memory");
}

// ---------------- x1 = relu(y[:, 768:896]) ----------------
__global__ void k_relu() {
    int i = blockIdx.x * blockDim.x + threadIdx.x;
    if (i < N_NODES * 32) {
        int n = i >> 5, j = (i & 31) * 4;
        float4 v = *(const float4*)(g_y + (size_t)n * YSTRIDE + NREL * DIM + j);
        v.x = fmaxf(v.x, 0.f); v.y = fmaxf(v.y, 0.f); v.z = fmaxf(v.z, 0.f); v.w = fmaxf(v.w, 0.f);
        *(float4*)(g_x1 + (size_t)n * DIM + j) = v;
    }
}

// ---------------- zero agg2 ----------------
__global__ void k_zero_agg2() {
    int i = blockIdx.x * blockDim.x + threadIdx.x;
    const int n4 = NOUT2 * NREL * DIM / 4;
    if (i < n4) ((float4*)g_agg2)[i] = make_float4(0.f, 0.f, 0.f, 0.f);
}

// ---------------- scatter2: agg2[dst, t, :] += x1[src, :]   (only dst < 25000) ----------------
__global__ __launch_bounds__(256) void k_scatter2(const int* __restrict__ ei, const int* __restrict__ et) {
    int gw = (int)((blockIdx.x * 256u + threadIdx.x) >> 5);
    if (gw >= NE) return;
    int dst = ei[NE + gw];
    if (dst >= NOUT2) return;
    int lane = threadIdx.x & 31;
    int src = ei[gw], t = et[gw];
    const float4 v = *(const float4*)(g_x1 + (size_t)src * DIM + lane * 4);
    float* p = g_agg2 + ((size_t)dst * NREL + t) * DIM + lane * 4;
    asm volatile("red.global.add.v4.f32 [%0], {%1, %2, %3, %4};"
                 :: "l"(p), "f"(v.x), "f"(v.y), "f"(v.z), "f"(v.w) : "memory");
}

// ---------------- GEMM2: x2[25000,128] = A[25000,896] @ B2[896,128] + bias2 ----------------
// A[n, r*128+d] = agg2[n,r,d] * inv[n,r];   A[n, 768+d] = x1[n,d]
__global__ __launch_bounds__(256) void k_gemm2(const float* __restrict__ bias2) {
    __shared__ float As[8][128];
    __shared__ float Bs[8][128];
    const int row0 = blockIdx.x * 128;
    const int tid = threadIdx.x;
    const int tx = tid & 15, ty = tid >> 4;
    unsigned long long acc[8][4];
    #pragma unroll
    for (int i = 0; i < 8; i++)
        #pragma unroll
        for (int j = 0; j < 4; j++) acc[i][j] = 0ull;
    const int ar = tid >> 1, ak = (tid & 1) * 4;
    const int bk = tid >> 5, bc = (tid & 31) * 4;
    const int arow = row0 + ar;
    for (int k0 = 0; k0 < K1; k0 += 8) {
        float4 av = make_float4(0.f, 0.f, 0.f, 0.f);
        if (arow < NOUT2) {
            if (k0 < NREL * DIM) {
                av = *(const float4*)(g_agg2 + (size_t)arow * (NREL * DIM) + k0 + ak);
                float s = g_inv[arow * NREL + (k0 >> 7)];
                av.x *= s; av.y *= s; av.z *= s; av.w *= s;
            } else {
                av = *(const float4*)(g_x1 + (size_t)arow * DIM + (k0 - NREL * DIM) + ak);
            }
        }
        As[ak + 0][ar] = av.x; As[ak + 1][ar] = av.y; As[ak + 2][ar] = av.z; As[ak + 3][ar] = av.w;
        *(float4*)&Bs[bk][bc] = *(const float4*)(g_B2 + (size_t)(k0 + bk) * DIM + bc);
        __syncthreads();
        #pragma unroll
        for (int k = 0; k < 8; k++) {
            float4 a0 = *(float4*)&As[k][ty * 8];
            float4 a1 = *(float4*)&As[k][ty * 8 + 4];
            unsigned long long b0 = *(unsigned long long*)&Bs[k][tx * 8 + 0];
            unsigned long long b1 = *(unsigned long long*)&Bs[k][tx * 8 + 2];
            unsigned long long b2 = *(unsigned long long*)&Bs[k][tx * 8 + 4];
            unsigned long long b3 = *(unsigned long long*)&Bs[k][tx * 8 + 6];
            float a8[8] = {a0.x, a0.y, a0.z, a0.w, a1.x, a1.y, a1.z, a1.w};
            #pragma unroll
            for (int i = 0; i < 8; i++) {
                unsigned long long a2 = pack2(a8[i]);
                ffma2(acc[i][0], a2, b0);
                ffma2(acc[i][1], a2, b1);
                ffma2(acc[i][2], a2, b2);
                ffma2(acc[i][3], a2, b3);
            }
        }
        __syncthreads();
    }
    #pragma unroll
    for (int i = 0; i < 8; i++) {
        int r = row0 + ty * 8 + i;
        if (r >= NOUT2) continue;
        #pragma unroll
        for (int j = 0; j < 4; j++) {
            int c = tx * 8 + j * 2;
            float lo = lo32(acc[i][j]) + bias2[c];
            float hi = hi32(acc[i][j]) + bias2[c + 1];
            *(float2*)(g_x2 + (size_t)r * DIM + c) = make_float2(lo, hi);
        }
    }
}

// ---------------- scorer: 64 pairs per block ----------------
// feat[512] = [h, p, h*p, |h-p|];  hid = relu(feat@sw1+sb1);  out = hid@sw2+sb2
__global__ __launch_bounds__(256) void k_scorer(const int* __restrict__ h_idx, const int* __restrict__ p_idx,
                                                const float* __restrict__ sw1, const float* __restrict__ sb1,
                                                const float* __restrict__ sw2, const float* __restrict__ sb2,
                                                float* __restrict__ out) {
    extern __shared__ float sm[];
    float* Ft  = sm;                    // [512][68] (K-major, padded)
    float* Bs  = sm + 512 * 68;         // [8][128]
    float* red = Bs + 8 * 128;          // [64][16]
    const int tid = threadIdx.x;
    const int tx = tid & 15, ty = tid >> 4;
    const int pair0 = blockIdx.x * 64;

    for (int idx = tid; idx < 64 * DIM; idx += 256) {
        int row = idx >> 7, d = idx & 127;
        int pr = pair0 + row;
        float hv = g_x2[(size_t)h_idx[pr] * DIM + d];
        float pv = g_x2[(size_t)(N_HERB + p_idx[pr]) * DIM + d];
        Ft[(d      ) * 68 + row] = hv;
        Ft[(128 + d) * 68 + row] = pv;
        Ft[(256 + d) * 68 + row] = hv * pv;
        Ft[(384 + d) * 68 + row] = fabsf(hv - pv);
    }

    unsigned long long acc[4][4];
    #pragma unroll
    for (int i = 0; i < 4; i++)
        #pragma unroll
        for (int j = 0; j < 4; j++) acc[i][j] = 0ull;
    const int bk = tid >> 5, bc = (tid & 31) * 4;

    for (int k0 = 0; k0 < 512; k0 += 8) {
        *(float4*)&Bs[bk * 128 + bc] = *(const float4*)(sw1 + (size_t)(k0 + bk) * DIM + bc);
        __syncthreads();   // also orders the Ft build on the first iteration
        #pragma unroll
        for (int k = 0; k < 8; k++) {
            float4 a = *(float4*)&Ft[(k0 + k) * 68 + ty * 4];
            unsigned long long b0 = *(unsigned long long*)&Bs[k * 128 + tx * 8 + 0];
            unsigned long long b1 = *(unsigned long long*)&Bs[k * 128 + tx * 8 + 2];
            unsigned long long b2 = *(unsigned long long*)&Bs[k * 128 + tx * 8 + 4];
            unsigned long long b3 = *(unsigned long long*)&Bs[k * 128 + tx * 8 + 6];
            float a4[4] = {a.x, a.y, a.z, a.w};
            #pragma unroll
            for (int i = 0; i < 4; i++) {
                unsigned long long a2 = pack2(a4[i]);
                ffma2(acc[i][0], a2, b0);
                ffma2(acc[i][1], a2, b1);
                ffma2(acc[i][2], a2, b2);
                ffma2(acc[i][3], a2, b3);
            }
        }
        __syncthreads();
    }

    float s[4] = {0.f, 0.f, 0.f, 0.f};
    #pragma unroll
    for (int i = 0; i < 4; i++) {
        #pragma unroll
        for (int j = 0; j < 4; j++) {
            int c = tx * 8 + j * 2;
            float lo = fmaxf(lo32(acc[i][j]) + sb1[c], 0.f);
            float hi = fmaxf(hi32(acc[i][j]) + sb1[c + 1], 0.f);
            s[i] += lo * sw2[c] + hi * sw2[c + 1];
        }
    }
    #pragma unroll
    for (int i = 0; i < 4; i++) red[(ty * 4 + i) * 16 + tx] = s[i];
    __syncthreads();
    if (tid < 64) {
        float t = 0.f;
        #pragma unroll
        for (int j = 0; j < 16; j++) t += red[tid * 16 + j];
        out[pair0 + tid] = t + sb2[0];
    }
}

// ---------------- launch ----------------
extern "C" void kernel_launch(void* const* d_in, const int* in_sizes, int n_in,
                              void* d_out, int out_size) {
    const int*   edge_index = (const int*)d_in[0];
    const int*   edge_type  = (const int*)d_in[1];
    const int*   h_idx      = (const int*)d_in[2];
    const int*   p_idx      = (const int*)d_in[3];
    const float* node_emb   = (const float*)d_in[4];
    const float* basis1 = (const float*)d_in[5];
    const float* comp1  = (const float*)d_in[6];
    const float* root1  = (const float*)d_in[7];
    const float* bias1  = (const float*)d_in[8];
    const float* basis2 = (const float*)d_in[9];
    const float* comp2  = (const float*)d_in[10];
    const float* root2  = (const float*)d_in[11];
    const float* bias2  = (const float*)d_in[12];
    const float* sw1 = (const float*)d_in[13];
    const float* sb1 = (const float*)d_in[14];
    const float* sw2 = (const float*)d_in[15];
    const float* sb2 = (const float*)d_in[16];
    float* out = (float*)d_out;

    const int scorer_smem = (512 * 68 + 8 * 128 + 64 * 16) * (int)sizeof(float); // 147456 B
    cudaFuncSetAttribute(k_scorer, cudaFuncAttributeMaxDynamicSharedMemorySize, scorer_smem);

    k_build_w<<<448, 256>>>(basis1, comp1, root1, 0);
    k_build_w<<<448, 256>>>(basis2, comp2, root2, 1);

    k_zero_cnt<<<(N_NODES * NREL + 255) / 256, 256>>>();
    k_count<<<(NE + 255) / 256, 256>>>(edge_index, edge_type);
    k_inv<<<(N_NODES * NREL + 255) / 256, 256>>>();

    // layer 1: transform-first, then edge scatter into the root-accumulator slice
    k_gemm1<<<dim3((N_NODES + 127) / 128, K1 / 128), 256>>>(node_emb, bias1);
    k_scatter1<<<(NE * 32 + 255) / 256, 256>>>(edge_index, edge_type);
    k_relu<<<(N_NODES * 32 + 255) / 256, 256>>>();

    // layer 2: aggregate-first (only dst < 25000), then fused transform
    k_zero_agg2<<<((NOUT2 * NREL * DIM / 4) + 255) / 256, 256>>>();
    k_scatter2<<<(NE * 32 + 255) / 256, 256>>>(edge_index, edge_type);
    k_gemm2<<<dim3((NOUT2 + 127) / 128, 1), 256>>>(bias2);

    // scorer
    k_scorer<<<NP / 64, 256, scorer_smem>>>(h_idx, p_idx, sw1, sb1, sw2, sb2, out);
}

// round 3
// speedup vs baseline: 1.2117x; 1.2117x over previous
#include <cuda_runtime.h>
#include <cuda_bf16.h>
#include <cstdint>

#define N_NODES 60000
#define N_HERB  5000
#define NOUT2   25000
#define DIM     128
#define NREL    6
#define NB      30
#define NE      600000
#define NP      40000
#define YSTRIDE 896

// ---------------- scratch ----------------
__device__ float g_y [(size_t)N_NODES * YSTRIDE];      // layer1 messages (0:768) + out accum (768:896)
__device__ float g_x1[(size_t)N_NODES * DIM];
__device__ float g_agg2[(size_t)NOUT2 * NREL * DIM];
__device__ float g_x2[(size_t)NOUT2 * DIM];
__device__ int   g_cnt[N_NODES * NREL];
__device__ float g_inv[N_NODES * NREL];
// split bf16 weights, transposed to [N][K] K-major, packed bf16x2 per u32
__device__ uint32_t g_BT1h[896 * 64], g_BT1l[896 * 64];   // layer1: [col][d-pair]
__device__ uint32_t g_BT2h[128 * 448], g_BT2l[128 * 448]; // layer2: [o][k-pair]
__device__ uint32_t g_SW1h[128 * 256], g_SW1l[128 * 256]; // scorer: [o][featk-pair]

// ---------------- helpers ----------------
__device__ __forceinline__ uint32_t smem_u32(const void* p) {
    uint32_t a;
    asm("{ .reg .u64 t; cvta.to.shared.u64 t, %1; cvt.u32.u64 %0, t; }" : "=r"(a) : "l"(p));
    return a;
}
__device__ __forceinline__ void ldm4(uint32_t* r, uint32_t addr) {
    asm volatile("ldmatrix.sync.aligned.m8n8.x4.shared.b16 {%0,%1,%2,%3}, [%4];"
        : "=r"(r[0]), "=r"(r[1]), "=r"(r[2]), "=r"(r[3]) : "r"(addr));
}
__device__ __forceinline__ void mma_bf16(float* d, const uint32_t* a, uint32_t b0, uint32_t b1) {
    asm volatile("mma.sync.aligned.m16n8k16.row.col.f32.bf16.bf16.f32 "
        "{%0,%1,%2,%3}, {%4,%5,%6,%7}, {%8,%9}, {%0,%1,%2,%3};"
        : "+f"(d[0]), "+f"(d[1]), "+f"(d[2]), "+f"(d[3])
        : "r"(a[0]), "r"(a[1]), "r"(a[2]), "r"(a[3]), "r"(b0), "r"(b1));
}
__device__ __forceinline__ uint32_t split_pack_hi(float2 f) {
    __nv_bfloat162 h;
    h.x = __float2bfloat16_rn(f.x); h.y = __float2bfloat16_rn(f.y);
    return *(uint32_t*)&h;
}
__device__ __forceinline__ uint32_t split_pack_lo(float2 f) {
    __nv_bfloat16 hx = __float2bfloat16_rn(f.x), hy = __float2bfloat16_rn(f.y);
    __nv_bfloat162 l;
    l.x = __float2bfloat16_rn(f.x - __bfloat162float(hx));
    l.y = __float2bfloat16_rn(f.y - __bfloat162float(hy));
    return *(uint32_t*)&l;
}

// smem tile geometry: 128 rows x 64 u32 (128 bf16), row stride 68 u32 = 272 B
#define TSTR 68
#define TILE_BYTES (128 * TSTR * 4)   // 34816

// ---------------- weight build (split bf16, transposed) ----------------
__global__ void k_build_w1(const float* __restrict__ basis, const float* __restrict__ comp,
                           const float* __restrict__ root) {
    int idx = blockIdx.x * blockDim.x + threadIdx.x;
    if (idx >= 896 * 64) return;
    int col = idx >> 6, j = idx & 63, d0 = j * 2;
    float w0, w1;
    if (col < 768) {
        int r = col >> 7, o = col & 127;
        w0 = 0.f; w1 = 0.f;
        #pragma unroll
        for (int b = 0; b < NB; b++) {
            float cc = comp[r * NB + b];
            w0 += cc * basis[b * 16384 + d0 * 128 + o];
            w1 += cc * basis[b * 16384 + (d0 + 1) * 128 + o];
        }
    } else {
        int o = col - 768;
        w0 = root[d0 * 128 + o]; w1 = root[(d0 + 1) * 128 + o];
    }
    float2 f = make_float2(w0, w1);
    g_BT1h[idx] = split_pack_hi(f);
    g_BT1l[idx] = split_pack_lo(f);
}
__global__ void k_build_w2(const float* __restrict__ basis, const float* __restrict__ comp,
                           const float* __restrict__ root) {
    int idx = blockIdx.x * blockDim.x + threadIdx.x;
    if (idx >= 128 * 448) return;
    int o = idx / 448, j = idx % 448, k0 = j * 2;
    float w0, w1;
    if (k0 < 768) {
        int r = k0 >> 7, d0 = k0 & 127;
        w0 = 0.f; w1 = 0.f;
        #pragma unroll
        for (int b = 0; b < NB; b++) {
            float cc = comp[r * NB + b];
            w0 += cc * basis[b * 16384 + d0 * 128 + o];
            w1 += cc * basis[b * 16384 + (d0 + 1) * 128 + o];
        }
    } else {
        int d0 = k0 - 768;
        w0 = root[d0 * 128 + o]; w1 = root[(d0 + 1) * 128 + o];
    }
    float2 f = make_float2(w0, w1);
    g_BT2h[idx] = split_pack_hi(f);
    g_BT2l[idx] = split_pack_lo(f);
}
__global__ void k_build_sw1t(const float* __restrict__ sw1) {
    int idx = blockIdx.x * blockDim.x + threadIdx.x;
    if (idx >= 128 * 256) return;
    int o = idx >> 8, j = idx & 255, k0 = j * 2;
    float2 f = make_float2(sw1[k0 * 128 + o], sw1[(k0 + 1) * 128 + o]);
    g_SW1h[idx] = split_pack_hi(f);
    g_SW1l[idx] = split_pack_lo(f);
}

// ---------------- counts ----------------
__global__ void k_zero_cnt() {
    int i = blockIdx.x * blockDim.x + threadIdx.x;
    if (i < N_NODES * NREL) g_cnt[i] = 0;
}
__global__ void k_count(const int* __restrict__ ei, const int* __restrict__ et) {
    int e = blockIdx.x * blockDim.x + threadIdx.x;
    if (e < NE) atomicAdd(&g_cnt[ei[NE + e] * NREL + et[e]], 1);
}
__global__ void k_inv() {
    int i = blockIdx.x * blockDim.x + threadIdx.x;
    if (i < N_NODES * NREL) {
        int c = g_cnt[i];
        g_inv[i] = 1.0f / (float)(c > 0 ? c : 1);
    }
}

// ---------------- GEMM1 (HMMA): y[60000,896] = X @ W1all (+bias on root cols) ----------------
__global__ __launch_bounds__(256) void k_gemm1_mma(const float* __restrict__ X, const float* __restrict__ bias1) {
    extern __shared__ char sm[];
    uint32_t* Ah = (uint32_t*)sm;
    uint32_t* Al = (uint32_t*)(sm + TILE_BYTES);
    uint32_t* Bh = (uint32_t*)(sm + 2 * TILE_BYTES);
    uint32_t* Bl = (uint32_t*)(sm + 3 * TILE_BYTES);
    const uint32_t sAh = smem_u32(Ah), sAl = smem_u32(Al), sBh = smem_u32(Bh), sBl = smem_u32(Bl);
    const int tid = threadIdx.x, lane = tid & 31, wid = tid >> 5;
    const int wm = wid & 3, wn = wid >> 2;
    const int lrow = lane & 15, lk = lane >> 4;
    const int m0 = blockIdx.x * 128, col0 = blockIdx.y * 128;

    // stage A (fp32 -> split bf16) and B (prebuilt)
    for (int i = tid; i < 128 * 64; i += 256) {
        int row = i >> 6, k2 = i & 63;
        int grow = m0 + row; if (grow >= N_NODES) grow = N_NODES - 1;
        float2 f = *(const float2*)(X + (size_t)grow * DIM + k2 * 2);
        Ah[row * TSTR + k2] = split_pack_hi(f);
        Al[row * TSTR + k2] = split_pack_lo(f);
        Bh[row * TSTR + k2] = g_BT1h[(size_t)(col0 + row) * 64 + k2];
        Bl[row * TSTR + k2] = g_BT1l[(size_t)(col0 + row) * 64 + k2];
    }
    __syncthreads();

    float acc[2][8][4];
    #pragma unroll
    for (int i = 0; i < 2; i++)
        #pragma unroll
        for (int j = 0; j < 8; j++)
            #pragma unroll
            for (int c = 0; c < 4; c++) acc[i][j][c] = 0.f;

    #pragma unroll
    for (int kk8 = 0; kk8 < 8; kk8++) {
        uint32_t ah[2][4], al[2][4], bh[4][4], bl[4][4];
        #pragma unroll
        for (int mt = 0; mt < 2; mt++) {
            uint32_t off = (uint32_t)((wm * 32 + mt * 16 + lrow) * 272 + kk8 * 32 + lk * 16);
            ldm4(ah[mt], sAh + off);
            ldm4(al[mt], sAl + off);
        }
        #pragma unroll
        for (int nt = 0; nt < 4; nt++) {
            uint32_t off = (uint32_t)((wn * 64 + nt * 16 + lrow) * 272 + kk8 * 32 + lk * 16);
            ldm4(bh[nt], sBh + off);
            ldm4(bl[nt], sBl + off);
        }
        #pragma unroll
        for (int mt = 0; mt < 2; mt++)
            #pragma unroll
            for (int nt = 0; nt < 4; nt++) {
                mma_bf16(acc[mt][2 * nt],     ah[mt], bh[nt][0], bh[nt][2]);
                mma_bf16(acc[mt][2 * nt + 1], ah[mt], bh[nt][1], bh[nt][3]);
                mma_bf16(acc[mt][2 * nt],     al[mt], bh[nt][0], bh[nt][2]);
                mma_bf16(acc[mt][2 * nt + 1], al[mt], bh[nt][1], bh[nt][3]);
                mma_bf16(acc[mt][2 * nt],     ah[mt], bl[nt][0], bl[nt][2]);
                mma_bf16(acc[mt][2 * nt + 1], ah[mt], bl[nt][1], bl[nt][3]);
            }
    }

    // epilogue
    const int g = lane >> 2, tc = lane & 3;
    const bool isbias = (blockIdx.y == 6);
    #pragma unroll
    for (int mt = 0; mt < 2; mt++) {
        #pragma unroll
        for (int nb = 0; nb < 8; nb++) {
            int col = col0 + wn * 64 + nb * 8 + tc * 2;
            float b0 = 0.f, b1 = 0.f;
            if (isbias) { b0 = bias1[col - 768]; b1 = bias1[col - 767]; }
            int r0 = m0 + wm * 32 + mt * 16 + g;
            if (r0 < N_NODES)
                *(float2*)(g_y + (size_t)r0 * YSTRIDE + col) =
                    make_float2(acc[mt][nb][0] + b0, acc[mt][nb][1] + b1);
            int r1 = r0 + 8;
            if (r1 < N_NODES)
                *(float2*)(g_y + (size_t)r1 * YSTRIDE + col) =
                    make_float2(acc[mt][nb][2] + b0, acc[mt][nb][3] + b1);
        }
    }
}

// ---------------- scatter1 ----------------
__global__ __launch_bounds__(256) void k_scatter1(const int* __restrict__ ei, const int* __restrict__ et) {
    int gw = (int)((blockIdx.x * 256u + threadIdx.x) >> 5);
    if (gw >= NE) return;
    int lane = threadIdx.x & 31;
    int src = ei[gw], dst = ei[NE + gw], t = et[gw];
    float s = g_inv[dst * NREL + t];
    const float4 v = *(const float4*)(g_y + (size_t)src * YSTRIDE + t * DIM + lane * 4);
    float* p = g_y + (size_t)dst * YSTRIDE + NREL * DIM + lane * 4;
    asm volatile("red.global.add.v4.f32 [%0], {%1, %2, %3, %4};"
                 :: "l"(p), "f"(v.x * s), "f"(v.y * s), "f"(v.z * s), "f"(v.w * s) : "memory");
}

__global__ void k_relu() {
    int i = blockIdx.x * blockDim.x + threadIdx.x;
    if (i < N_NODES * 32) {
        int n = i >> 5, j = (i & 31) * 4;
        float4 v = *(const float4*)(g_y + (size_t)n * YSTRIDE + NREL * DIM + j);
        v.x = fmaxf(v.x, 0.f); v.y = fmaxf(v.y, 0.f); v.z = fmaxf(v.z, 0.f); v.w = fmaxf(v.w, 0.f);
        *(float4*)(g_x1 + (size_t)n * DIM + j) = v;
    }
}

__global__ void k_zero_agg2() {
    int i = blockIdx.x * blockDim.x + threadIdx.x;
    const int n4 = NOUT2 * NREL * DIM / 4;
    if (i < n4) ((float4*)g_agg2)[i] = make_float4(0.f, 0.f, 0.f, 0.f);
}

__global__ __launch_bounds__(256) void k_scatter2(const int* __restrict__ ei, const int* __restrict__ et) {
    int gw = (int)((blockIdx.x * 256u + threadIdx.x) >> 5);
    if (gw >= NE) return;
    int dst = ei[NE + gw];
    if (dst >= NOUT2) return;
    int lane = threadIdx.x & 31;
    int src = ei[gw], t = et[gw];
    const float4 v = *(const float4*)(g_x1 + (size_t)src * DIM + lane * 4);
    float* p = g_agg2 + ((size_t)dst * NREL + t) * DIM + lane * 4;
    asm volatile("red.global.add.v4.f32 [%0], {%1, %2, %3, %4};"
                 :: "l"(p), "f"(v.x), "f"(v.y), "f"(v.z), "f"(v.w) : "memory");
}

// ---------------- GEMM2 (HMMA): x2[25000,128] = A[25000,896] @ B2 + bias2 ----------------
__global__ __launch_bounds__(256) void k_gemm2_mma(const float* __restrict__ bias2) {
    extern __shared__ char sm[];
    uint32_t* Ah = (uint32_t*)sm;
    uint32_t* Al = (uint32_t*)(sm + TILE_BYTES);
    uint32_t* Bh = (uint32_t*)(sm + 2 * TILE_BYTES);
    uint32_t* Bl = (uint32_t*)(sm + 3 * TILE_BYTES);
    const uint32_t sAh = smem_u32(Ah), sAl = smem_u32(Al), sBh = smem_u32(Bh), sBl = smem_u32(Bl);
    const int tid = threadIdx.x, lane = tid & 31, wid = tid >> 5;
    const int wm = wid & 3, wn = wid >> 2;
    const int lrow = lane & 15, lk = lane >> 4;
    const int m0 = blockIdx.x * 128;

    float acc[2][8][4];
    #pragma unroll
    for (int i = 0; i < 2; i++)
        #pragma unroll
        for (int j = 0; j < 8; j++)
            #pragma unroll
            for (int c = 0; c < 4; c++) acc[i][j][c] = 0.f;

    for (int c = 0; c < 7; c++) {
        for (int i = tid; i < 128 * 64; i += 256) {
            int row = i >> 6, k2 = i & 63;
            int grow = m0 + row; if (grow >= NOUT2) grow = NOUT2 - 1;
            float2 f;
            if (c < 6) {
                f = *(const float2*)(g_agg2 + ((size_t)grow * NREL + c) * DIM + k2 * 2);
                float s = g_inv[grow * NREL + c];
                f.x *= s; f.y *= s;
            } else {
                f = *(const float2*)(g_x1 + (size_t)grow * DIM + k2 * 2);
            }
            Ah[row * TSTR + k2] = split_pack_hi(f);
            Al[row * TSTR + k2] = split_pack_lo(f);
            Bh[row * TSTR + k2] = g_BT2h[(size_t)row * 448 + c * 64 + k2];
            Bl[row * TSTR + k2] = g_BT2l[(size_t)row * 448 + c * 64 + k2];
        }
        __syncthreads();

        #pragma unroll
        for (int kk8 = 0; kk8 < 8; kk8++) {
            uint32_t ah[2][4], al[2][4], bh[4][4], bl[4][4];
            #pragma unroll
            for (int mt = 0; mt < 2; mt++) {
                uint32_t off = (uint32_t)((wm * 32 + mt * 16 + lrow) * 272 + kk8 * 32 + lk * 16);
                ldm4(ah[mt], sAh + off);
                ldm4(al[mt], sAl + off);
            }
            #pragma unroll
            for (int nt = 0; nt < 4; nt++) {
                uint32_t off = (uint32_t)((wn * 64 + nt * 16 + lrow) * 272 + kk8 * 32 + lk * 16);
                ldm4(bh[nt], sBh + off);
                ldm4(bl[nt], sBl + off);
            }
            #pragma unroll
            for (int mt = 0; mt < 2; mt++)
                #pragma unroll
                for (int nt = 0; nt < 4; nt++) {
                    mma_bf16(acc[mt][2 * nt],     ah[mt], bh[nt][0], bh[nt][2]);
                    mma_bf16(acc[mt][2 * nt + 1], ah[mt], bh[nt][1], bh[nt][3]);
                    mma_bf16(acc[mt][2 * nt],     al[mt], bh[nt][0], bh[nt][2]);
                    mma_bf16(acc[mt][2 * nt + 1], al[mt], bh[nt][1], bh[nt][3]);
                    mma_bf16(acc[mt][2 * nt],     ah[mt], bl[nt][0], bl[nt][2]);
                    mma_bf16(acc[mt][2 * nt + 1], ah[mt], bl[nt][1], bl[nt][3]);
                }
        }
        __syncthreads();
    }

    const int g = lane >> 2, tc = lane & 3;
    #pragma unroll
    for (int mt = 0; mt < 2; mt++) {
        #pragma unroll
        for (int nb = 0; nb < 8; nb++) {
            int col = wn * 64 + nb * 8 + tc * 2;
            float b0 = bias2[col], b1 = bias2[col + 1];
            int r0 = m0 + wm * 32 + mt * 16 + g;
            if (r0 < NOUT2)
                *(float2*)(g_x2 + (size_t)r0 * DIM + col) =
                    make_float2(acc[mt][nb][0] + b0, acc[mt][nb][1] + b1);
            int r1 = r0 + 8;
            if (r1 < NOUT2)
                *(float2*)(g_x2 + (size_t)r1 * DIM + col) =
                    make_float2(acc[mt][nb][2] + b0, acc[mt][nb][3] + b1);
        }
    }
}

// ---------------- scorer (HMMA): hid = relu(F@SW1+sb1); out = hid@sw2+sb2 ----------------
__global__ __launch_bounds__(256) void k_scorer_mma(const int* __restrict__ h_idx, const int* __restrict__ p_idx,
                                                    const float* __restrict__ sb1, const float* __restrict__ sw2,
                                                    const float* __restrict__ sb2, float* __restrict__ out) {
    extern __shared__ char sm[];
    uint32_t* Ah = (uint32_t*)sm;
    uint32_t* Al = (uint32_t*)(sm + TILE_BYTES);
    uint32_t* Bh = (uint32_t*)(sm + 2 * TILE_BYTES);
    uint32_t* Bl = (uint32_t*)(sm + 3 * TILE_BYTES);
    const uint32_t sAh = smem_u32(Ah), sAl = smem_u32(Al), sBh = smem_u32(Bh), sBl = smem_u32(Bl);
    const int tid = threadIdx.x, lane = tid & 31, wid = tid >> 5;
    const int wm = wid & 3, wn = wid >> 2;
    const int lrow = lane & 15, lk = lane >> 4;
    const int pair0 = blockIdx.x * 128;

    float acc[2][8][4];
    #pragma unroll
    for (int i = 0; i < 2; i++)
        #pragma unroll
        for (int j = 0; j < 8; j++)
            #pragma unroll
            for (int c = 0; c < 4; c++) acc[i][j][c] = 0.f;

    for (int c = 0; c < 4; c++) {
        for (int i = tid; i < 128 * 64; i += 256) {
            int row = i >> 6, k2 = i & 63;
            int pr = pair0 + row; if (pr >= NP) pr = NP - 1;
            float2 h = *(const float2*)(g_x2 + (size_t)h_idx[pr] * DIM + k2 * 2);
            float2 p = *(const float2*)(g_x2 + (size_t)(N_HERB + p_idx[pr]) * DIM + k2 * 2);
            float2 f;
            if (c == 0) f = h;
            else if (c == 1) f = p;
            else if (c == 2) f = make_float2(h.x * p.x, h.y * p.y);
            else f = make_float2(fabsf(h.x - p.x), fabsf(h.y - p.y));
            Ah[row * TSTR + k2] = split_pack_hi(f);
            Al[row * TSTR + k2] = split_pack_lo(f);
            Bh[row * TSTR + k2] = g_SW1h[(size_t)row * 256 + c * 64 + k2];
            Bl[row * TSTR + k2] = g_SW1l[(size_t)row * 256 + c * 64 + k2];
        }
        __syncthreads();

        #pragma unroll
        for (int kk8 = 0; kk8 < 8; kk8++) {
            uint32_t ah[2][4], al[2][4], bh[4][4], bl[4][4];
            #pragma unroll
            for (int mt = 0; mt < 2; mt++) {
                uint32_t off = (uint32_t)((wm * 32 + mt * 16 + lrow) * 272 + kk8 * 32 + lk * 16);
                ldm4(ah[mt], sAh + off);
                ldm4(al[mt], sAl + off);
            }
            #pragma unroll
            for (int nt = 0; nt < 4; nt++) {
                uint32_t off = (uint32_t)((wn * 64 + nt * 16 + lrow) * 272 + kk8 * 32 + lk * 16);
                ldm4(bh[nt], sBh + off);
                ldm4(bl[nt], sBl + off);
            }
            #pragma unroll
            for (int mt = 0; mt < 2; mt++)
                #pragma unroll
                for (int nt = 0; nt < 4; nt++) {
                    mma_bf16(acc[mt][2 * nt],     ah[mt], bh[nt][0], bh[nt][2]);
                    mma_bf16(acc[mt][2 * nt + 1], ah[mt], bh[nt][1], bh[nt][3]);
                    mma_bf16(acc[mt][2 * nt],     al[mt], bh[nt][0], bh[nt][2]);
                    mma_bf16(acc[mt][2 * nt + 1], al[mt], bh[nt][1], bh[nt][3]);
                    mma_bf16(acc[mt][2 * nt],     ah[mt], bl[nt][0], bl[nt][2]);
                    mma_bf16(acc[mt][2 * nt + 1], ah[mt], bl[nt][1], bl[nt][3]);
                }
        }
        __syncthreads();
    }

    // epilogue: relu + dot(sw2) + per-row reduce
    __syncthreads();                         // all ldmatrix reads done; smem reusable
    float* s_part = (float*)sm;              // [128][2]
    const int g = lane >> 2, tc = lane & 3;
    #pragma unroll
    for (int mt = 0; mt < 2; mt++) {
        float s0 = 0.f, s1 = 0.f;
        #pragma unroll
        for (int nb = 0; nb < 8; nb++) {
            int col = wn * 64 + nb * 8 + tc * 2;
            float w0 = sw2[col], w1 = sw2[col + 1];
            float bb0 = sb1[col], bb1 = sb1[col + 1];
            s0 += fmaxf(acc[mt][nb][0] + bb0, 0.f) * w0 + fmaxf(acc[mt][nb][1] + bb1, 0.f) * w1;
            s1 += fmaxf(acc[mt][nb][2] + bb0, 0.f) * w0 + fmaxf(acc[mt][nb][3] + bb1, 0.f) * w1;
        }
        s0 += __shfl_xor_sync(0xffffffff, s0, 1); s0 += __shfl_xor_sync(0xffffffff, s0, 2);
        s1 += __shfl_xor_sync(0xffffffff, s1, 1); s1 += __shfl_xor_sync(0xffffffff, s1, 2);
        if (tc == 0) {
            int r0 = wm * 32 + mt * 16 + g;
            s_part[r0 * 2 + wn] = s0;
            s_part[(r0 + 8) * 2 + wn] = s1;
        }
    }
    __syncthreads();
    if (tid < 128) {
        int pr = pair0 + tid;
        if (pr < NP) out[pr] = s_part[tid * 2] + s_part[tid * 2 + 1] + sb2[0];
    }
}

// ---------------- launch ----------------
extern "C" void kernel_launch(void* const* d_in, const int* in_sizes, int n_in,
                              void* d_out, int out_size) {
    const int*   edge_index = (const int*)d_in[0];
    const int*   edge_type  = (const int*)d_in[1];
    const int*   h_idx      = (const int*)d_in[2];
    const int*   p_idx      = (const int*)d_in[3];
    const float* node_emb   = (const float*)d_in[4];
    const float* basis1 = (const float*)d_in[5];
    const float* comp1  = (const float*)d_in[6];
    const float* root1  = (const float*)d_in[7];
    const float* bias1  = (const float*)d_in[8];
    const float* basis2 = (const float*)d_in[9];
    const float* comp2  = (const float*)d_in[10];
    const float* root2  = (const float*)d_in[11];
    const float* bias2  = (const float*)d_in[12];
    const float* sw1 = (const float*)d_in[13];
    const float* sb1 = (const float*)d_in[14];
    const float* sw2 = (const float*)d_in[15];
    const float* sb2 = (const float*)d_in[16];
    float* out = (float*)d_out;

    const int smem = 4 * TILE_BYTES;   // 139264 B
    cudaFuncSetAttribute(k_gemm1_mma, cudaFuncAttributeMaxDynamicSharedMemorySize, smem);
    cudaFuncSetAttribute(k_gemm2_mma, cudaFuncAttributeMaxDynamicSharedMemorySize, smem);
    cudaFuncSetAttribute(k_scorer_mma, cudaFuncAttributeMaxDynamicSharedMemorySize, smem);

    k_build_w1<<<(896 * 64 + 255) / 256, 256>>>(basis1, comp1, root1);
    k_build_w2<<<(128 * 448 + 255) / 256, 256>>>(basis2, comp2, root2);
    k_build_sw1t<<<(128 * 256 + 255) / 256, 256>>>(sw1);

    k_zero_cnt<<<(N_NODES * NREL + 255) / 256, 256>>>();
    k_count<<<(NE + 255) / 256, 256>>>(edge_index, edge_type);
    k_inv<<<(N_NODES * NREL + 255) / 256, 256>>>();

    k_gemm1_mma<<<dim3((N_NODES + 127) / 128, 7), 256, smem>>>(node_emb, bias1);
    k_scatter1<<<(NE * 32 + 255) / 256, 256>>>(edge_index, edge_type);
    k_relu<<<(N_NODES * 32 + 255) / 256, 256>>>();

    k_zero_agg2<<<((NOUT2 * NREL * DIM / 4) + 255) / 256, 256>>>();
    k_scatter2<<<(NE * 32 + 255) / 256, 256>>>(edge_index, edge_type);
    k_gemm2_mma<<<(NOUT2 + 127) / 128, 256, smem>>>(bias2);

    k_scorer_mma<<<(NP + 127) / 128, 256, smem>>>(h_idx, p_idx, sb1, sw2, sb2, out);
}

// round 5
// speedup vs baseline: 1.3421x; 1.1076x over previous
#include <cuda_runtime.h>
#include <cuda_bf16.h>
#include <cstdint>

#define N_NODES 60000
#define N_HERB  5000
#define NOUT2   25000
#define DIM     128
#define NREL    6
#define NB      30
#define NE      600000
#define NP      40000
#define NSEG1   (N_NODES * NREL)   // 360000
#define NSEG2   (NOUT2 * NREL)     // 150000
#define SCAN_BLK 1024
#define NBLK    ((NSEG1 + SCAN_BLK - 1) / SCAN_BLK)   // 352

// ---------------- scratch ----------------
__device__ float g_agg1[(size_t)NSEG1 * DIM];          // layer-1 per-(dst,rel) means
__device__ float g_x1[(size_t)N_NODES * DIM];
__device__ float g_agg2[(size_t)NSEG2 * DIM];          // layer-2 per-(dst,rel) means
__device__ float g_x2[(size_t)NOUT2 * DIM];
__device__ int   g_cnt[NSEG1];
__device__ int   g_off[NSEG1 + 1];
__device__ int   g_cursor[NSEG1];
__device__ int   g_esrc[NE];
__device__ int   g_bsum[NBLK], g_bpre[NBLK];
// split bf16 weights, transposed: [out_col][k-pair] (K-major), packed bf16x2 per u32
__device__ uint32_t g_BT1h[128 * 448], g_BT1l[128 * 448];  // layer1: k = r*128+d | 768+d(root)
__device__ uint32_t g_BT2h[128 * 448], g_BT2l[128 * 448];  // layer2 same shape
__device__ uint32_t g_SW1h[128 * 256], g_SW1l[128 * 256];  // scorer: k = feature index

// ---------------- helpers ----------------
__device__ __forceinline__ uint32_t smem_u32(const void* p) {
    uint32_t a;
    asm("{ .reg .u64 t; cvta.to.shared.u64 t, %1; cvt.u32.u64 %0, t; }" : "=r"(a) : "l"(p));
    return a;
}
__device__ __forceinline__ void ldm4(uint32_t* r, uint32_t addr) {
    asm volatile("ldmatrix.sync.aligned.m8n8.x4.shared.b16 {%0,%1,%2,%3}, [%4];"
        : "=r"(r[0]), "=r"(r[1]), "=r"(r[2]), "=r"(r[3]) : "r"(addr));
}
__device__ __forceinline__ void mma_bf16(float* d, const uint32_t* a, uint32_t b0, uint32_t b1) {
    asm volatile("mma.sync.aligned.m16n8k16.row.col.f32.bf16.bf16.f32 "
        "{%0,%1,%2,%3}, {%4,%5,%6,%7}, {%8,%9}, {%0,%1,%2,%3};"
        : "+f"(d[0]), "+f"(d[1]), "+f"(d[2]), "+f"(d[3])
        : "r"(a[0]), "r"(a[1]), "r"(a[2]), "r"(a[3]), "r"(b0), "r"(b1));
}
__device__ __forceinline__ uint32_t split_pack_hi(float2 f) {
    __nv_bfloat162 h;
    h.x = __float2bfloat16_rn(f.x); h.y = __float2bfloat16_rn(f.y);
    return *(uint32_t*)&h;
}
__device__ __forceinline__ uint32_t split_pack_lo(float2 f) {
    __nv_bfloat16 hx = __float2bfloat16_rn(f.x), hy = __float2bfloat16_rn(f.y);
    __nv_bfloat162 l;
    l.x = __float2bfloat16_rn(f.x - __bfloat162float(hx));
    l.y = __float2bfloat16_rn(f.y - __bfloat162float(hy));
    return *(uint32_t*)&l;
}

#define TSTR 68
#define TILE_BYTES (128 * TSTR * 4)   // 34816

// ---------------- weight build: B' rows k = r*128+d (r<6) | 768+d (root); cols o ----------------
__global__ void k_build_w1(const float* __restrict__ basis, const float* __restrict__ comp,
                           const float* __restrict__ root) {
    int idx = blockIdx.x * blockDim.x + threadIdx.x;
    if (idx >= 128 * 448) return;
    int o = idx / 448, j = idx % 448, k0 = j * 2;
    float w0, w1;
    if (k0 < 768) {
        int r = k0 >> 7, d0 = k0 & 127;
        w0 = 0.f; w1 = 0.f;
        #pragma unroll
        for (int b = 0; b < NB; b++) {
            float cc = comp[r * NB + b];
            w0 += cc * basis[b * 16384 + d0 * 128 + o];
            w1 += cc * basis[b * 16384 + (d0 + 1) * 128 + o];
        }
    } else {
        int d0 = k0 - 768;
        w0 = root[d0 * 128 + o]; w1 = root[(d0 + 1) * 128 + o];
    }
    float2 f = make_float2(w0, w1);
    g_BT1h[idx] = split_pack_hi(f);
    g_BT1l[idx] = split_pack_lo(f);
}
__global__ void k_build_w2(const float* __restrict__ basis, const float* __restrict__ comp,
                           const float* __restrict__ root) {
    int idx = blockIdx.x * blockDim.x + threadIdx.x;
    if (idx >= 128 * 448) return;
    int o = idx / 448, j = idx % 448, k0 = j * 2;
    float w0, w1;
    if (k0 < 768) {
        int r = k0 >> 7, d0 = k0 & 127;
        w0 = 0.f; w1 = 0.f;
        #pragma unroll
        for (int b = 0; b < NB; b++) {
            float cc = comp[r * NB + b];
            w0 += cc * basis[b * 16384 + d0 * 128 + o];
            w1 += cc * basis[b * 16384 + (d0 + 1) * 128 + o];
        }
    } else {
        int d0 = k0 - 768;
        w0 = root[d0 * 128 + o]; w1 = root[(d0 + 1) * 128 + o];
    }
    float2 f = make_float2(w0, w1);
    g_BT2h[idx] = split_pack_hi(f);
    g_BT2l[idx] = split_pack_lo(f);
}
__global__ void k_build_sw1t(const float* __restrict__ sw1) {
    int idx = blockIdx.x * blockDim.x + threadIdx.x;
    if (idx >= 128 * 256) return;
    int o = idx >> 8, j = idx & 255, k0 = j * 2;
    float2 f = make_float2(sw1[k0 * 128 + o], sw1[(k0 + 1) * 128 + o]);
    g_SW1h[idx] = split_pack_hi(f);
    g_SW1l[idx] = split_pack_lo(f);
}

// ---------------- CSR build ----------------
__global__ void k_zero_cnt() {
    int i = blockIdx.x * blockDim.x + threadIdx.x;
    if (i < NSEG1) g_cnt[i] = 0;
}
__global__ void k_count(const int* __restrict__ ei, const int* __restrict__ et) {
    int e = blockIdx.x * blockDim.x + threadIdx.x;
    if (e < NE) atomicAdd(&g_cnt[ei[NE + e] * NREL + et[e]], 1);
}
__global__ __launch_bounds__(SCAN_BLK) void k_scan_a() {
    __shared__ int sm[SCAN_BLK];
    int t = threadIdx.x;
    int gid = blockIdx.x * SCAN_BLK + t;
    int v = (gid < NSEG1) ? g_cnt[gid] : 0;
    sm[t] = v;
    __syncthreads();
    for (int d = 1; d < SCAN_BLK; d <<= 1) {
        int x = (t >= d) ? sm[t - d] : 0;
        __syncthreads();
        sm[t] += x;
        __syncthreads();
    }
    if (gid < NSEG1) g_off[gid] = sm[t] - v;        // exclusive within block
    if (t == SCAN_BLK - 1) g_bsum[blockIdx.x] = sm[t];
}
__global__ __launch_bounds__(512) void k_scan_b() {
    __shared__ int sm[512];
    int t = threadIdx.x;
    int v = (t < NBLK) ? g_bsum[t] : 0;
    sm[t] = v;
    __syncthreads();
    for (int d = 1; d < 512; d <<= 1) {
        int x = (t >= d) ? sm[t - d] : 0;
        __syncthreads();
        sm[t] += x;
        __syncthreads();
    }
    if (t < NBLK) g_bpre[t] = sm[t] - v;            // exclusive across blocks
}
__global__ __launch_bounds__(SCAN_BLK) void k_scan_c() {
    int gid = blockIdx.x * SCAN_BLK + threadIdx.x;
    if (gid < NSEG1) {
        int o = g_off[gid] + g_bpre[blockIdx.x];
        g_off[gid] = o;
        g_cursor[gid] = o;
    }
    if (gid == 0) g_off[NSEG1] = NE;
}
__global__ void k_fill(const int* __restrict__ ei, const int* __restrict__ et) {
    int e = blockIdx.x * blockDim.x + threadIdx.x;
    if (e < NE) {
        int seg = ei[NE + e] * NREL + et[e];
        int pos = atomicAdd(&g_cursor[seg], 1);
        g_esrc[pos] = ei[e];
    }
}

// ---------------- gathers: agg[seg] = mean_{e in seg} X[src(e)] ----------------
// NOTE: device globals referenced INSIDE the kernel (never passed from host).
__global__ __launch_bounds__(256) void k_gather1(const float* __restrict__ X) {
    int w = (int)((blockIdx.x * 256u + threadIdx.x) >> 5);
    if (w >= NSEG1) return;
    int lane = threadIdx.x & 31;
    int s0 = g_off[w], s1 = g_off[w + 1];
    float4 acc = make_float4(0.f, 0.f, 0.f, 0.f);
    for (int e = s0; e < s1; e++) {
        const float4 v = *(const float4*)(X + (size_t)g_esrc[e] * DIM + lane * 4);
        acc.x += v.x; acc.y += v.y; acc.z += v.z; acc.w += v.w;
    }
    float sc = (s1 > s0) ? 1.f / (float)(s1 - s0) : 0.f;
    *(float4*)(g_agg1 + (size_t)w * DIM + lane * 4) =
        make_float4(acc.x * sc, acc.y * sc, acc.z * sc, acc.w * sc);
}
__global__ __launch_bounds__(256) void k_gather2() {
    int w = (int)((blockIdx.x * 256u + threadIdx.x) >> 5);
    if (w >= NSEG2) return;
    int lane = threadIdx.x & 31;
    int s0 = g_off[w], s1 = g_off[w + 1];
    float4 acc = make_float4(0.f, 0.f, 0.f, 0.f);
    for (int e = s0; e < s1; e++) {
        const float4 v = *(const float4*)(g_x1 + (size_t)g_esrc[e] * DIM + lane * 4);
        acc.x += v.x; acc.y += v.y; acc.z += v.z; acc.w += v.w;
    }
    float sc = (s1 > s0) ? 1.f / (float)(s1 - s0) : 0.f;
    *(float4*)(g_agg2 + (size_t)w * DIM + lane * 4) =
        make_float4(acc.x * sc, acc.y * sc, acc.z * sc, acc.w * sc);
}

// ---------------- GEMM1 (HMMA): x1 = relu([agg1 | node_emb] @ B1' + bias1) ----------------
__global__ __launch_bounds__(256) void k_gemm1_mma(const float* __restrict__ X, const float* __restrict__ bias1) {
    extern __shared__ char sm[];
    uint32_t* Ah = (uint32_t*)sm;
    uint32_t* Al = (uint32_t*)(sm + TILE_BYTES);
    uint32_t* Bh = (uint32_t*)(sm + 2 * TILE_BYTES);
    uint32_t* Bl = (uint32_t*)(sm + 3 * TILE_BYTES);
    const uint32_t sAh = smem_u32(Ah), sAl = smem_u32(Al), sBh = smem_u32(Bh), sBl = smem_u32(Bl);
    const int tid = threadIdx.x, lane = tid & 31, wid = tid >> 5;
    const int wm = wid & 3, wn = wid >> 2;
    const int lrow = lane & 15, lk = lane >> 4;
    const int m0 = blockIdx.x * 128;

    float acc[2][8][4];
    #pragma unroll
    for (int i = 0; i < 2; i++)
        #pragma unroll
        for (int j = 0; j < 8; j++)
            #pragma unroll
            for (int c = 0; c < 4; c++) acc[i][j][c] = 0.f;

    for (int c = 0; c < 7; c++) {
        for (int i = tid; i < 128 * 64; i += 256) {
            int row = i >> 6, k2 = i & 63;
            int grow = m0 + row; if (grow >= N_NODES) grow = N_NODES - 1;
            float2 f;
            if (c < 6) f = *(const float2*)(g_agg1 + ((size_t)grow * NREL + c) * DIM + k2 * 2);
            else       f = *(const float2*)(X + (size_t)grow * DIM + k2 * 2);
            Ah[row * TSTR + k2] = split_pack_hi(f);
            Al[row * TSTR + k2] = split_pack_lo(f);
            Bh[row * TSTR + k2] = g_BT1h[(size_t)row * 448 + c * 64 + k2];
            Bl[row * TSTR + k2] = g_BT1l[(size_t)row * 448 + c * 64 + k2];
        }
        __syncthreads();
        #pragma unroll
        for (int kk8 = 0; kk8 < 8; kk8++) {
            uint32_t ah[2][4], al[2][4], bh[4][4], bl[4][4];
            #pragma unroll
            for (int mt = 0; mt < 2; mt++) {
                uint32_t off = (uint32_t)((wm * 32 + mt * 16 + lrow) * 272 + kk8 * 32 + lk * 16);
                ldm4(ah[mt], sAh + off);
                ldm4(al[mt], sAl + off);
            }
            #pragma unroll
            for (int nt = 0; nt < 4; nt++) {
                uint32_t off = (uint32_t)((wn * 64 + nt * 16 + lrow) * 272 + kk8 * 32 + lk * 16);
                ldm4(bh[nt], sBh + off);
                ldm4(bl[nt], sBl + off);
            }
            #pragma unroll
            for (int mt = 0; mt < 2; mt++)
                #pragma unroll
                for (int nt = 0; nt < 4; nt++) {
                    mma_bf16(acc[mt][2 * nt],     ah[mt], bh[nt][0], bh[nt][2]);
                    mma_bf16(acc[mt][2 * nt + 1], ah[mt], bh[nt][1], bh[nt][3]);
                    mma_bf16(acc[mt][2 * nt],     al[mt], bh[nt][0], bh[nt][2]);
                    mma_bf16(acc[mt][2 * nt + 1], al[mt], bh[nt][1], bh[nt][3]);
                    mma_bf16(acc[mt][2 * nt],     ah[mt], bl[nt][0], bl[nt][2]);
                    mma_bf16(acc[mt][2 * nt + 1], ah[mt], bl[nt][1], bl[nt][3]);
                }
        }
        __syncthreads();
    }

    const int g = lane >> 2, tc = lane & 3;
    #pragma unroll
    for (int mt = 0; mt < 2; mt++) {
        #pragma unroll
        for (int nb = 0; nb < 8; nb++) {
            int col = wn * 64 + nb * 8 + tc * 2;
            float b0 = bias1[col], b1 = bias1[col + 1];
            int r0 = m0 + wm * 32 + mt * 16 + g;
            if (r0 < N_NODES)
                *(float2*)(g_x1 + (size_t)r0 * DIM + col) =
                    make_float2(fmaxf(acc[mt][nb][0] + b0, 0.f), fmaxf(acc[mt][nb][1] + b1, 0.f));
            int r1 = r0 + 8;
            if (r1 < N_NODES)
                *(float2*)(g_x1 + (size_t)r1 * DIM + col) =
                    make_float2(fmaxf(acc[mt][nb][2] + b0, 0.f), fmaxf(acc[mt][nb][3] + b1, 0.f));
        }
    }
}

// ---------------- GEMM2 (HMMA): x2 = [agg2 | x1] @ B2' + bias2 ----------------
__global__ __launch_bounds__(256) void k_gemm2_mma(const float* __restrict__ bias2) {
    extern __shared__ char sm[];
    uint32_t* Ah = (uint32_t*)sm;
    uint32_t* Al = (uint32_t*)(sm + TILE_BYTES);
    uint32_t* Bh = (uint32_t*)(sm + 2 * TILE_BYTES);
    uint32_t* Bl = (uint32_t*)(sm + 3 * TILE_BYTES);
    const uint32_t sAh = smem_u32(Ah), sAl = smem_u32(Al), sBh = smem_u32(Bh), sBl = smem_u32(Bl);
    const int tid = threadIdx.x, lane = tid & 31, wid = tid >> 5;
    const int wm = wid & 3, wn = wid >> 2;
    const int lrow = lane & 15, lk = lane >> 4;
    const int m0 = blockIdx.x * 128;

    float acc[2][8][4];
    #pragma unroll
    for (int i = 0; i < 2; i++)
        #pragma unroll
        for (int j = 0; j < 8; j++)
            #pragma unroll
            for (int c = 0; c < 4; c++) acc[i][j][c] = 0.f;

    for (int c = 0; c < 7; c++) {
        for (int i = tid; i < 128 * 64; i += 256) {
            int row = i >> 6, k2 = i & 63;
            int grow = m0 + row; if (grow >= NOUT2) grow = NOUT2 - 1;
            float2 f;
            if (c < 6) f = *(const float2*)(g_agg2 + ((size_t)grow * NREL + c) * DIM + k2 * 2);
            else       f = *(const float2*)(g_x1 + (size_t)grow * DIM + k2 * 2);
            Ah[row * TSTR + k2] = split_pack_hi(f);
            Al[row * TSTR + k2] = split_pack_lo(f);
            Bh[row * TSTR + k2] = g_BT2h[(size_t)row * 448 + c * 64 + k2];
            Bl[row * TSTR + k2] = g_BT2l[(size_t)row * 448 + c * 64 + k2];
        }
        __syncthreads();
        #pragma unroll
        for (int kk8 = 0; kk8 < 8; kk8++) {
            uint32_t ah[2][4], al[2][4], bh[4][4], bl[4][4];
            #pragma unroll
            for (int mt = 0; mt < 2; mt++) {
                uint32_t off = (uint32_t)((wm * 32 + mt * 16 + lrow) * 272 + kk8 * 32 + lk * 16);
                ldm4(ah[mt], sAh + off);
                ldm4(al[mt], sAl + off);
            }
            #pragma unroll
            for (int nt = 0; nt < 4; nt++) {
                uint32_t off = (uint32_t)((wn * 64 + nt * 16 + lrow) * 272 + kk8 * 32 + lk * 16);
                ldm4(bh[nt], sBh + off);
                ldm4(bl[nt], sBl + off);
            }
            #pragma unroll
            for (int mt = 0; mt < 2; mt++)
                #pragma unroll
                for (int nt = 0; nt < 4; nt++) {
                    mma_bf16(acc[mt][2 * nt],     ah[mt], bh[nt][0], bh[nt][2]);
                    mma_bf16(acc[mt][2 * nt + 1], ah[mt], bh[nt][1], bh[nt][3]);
                    mma_bf16(acc[mt][2 * nt],     al[mt], bh[nt][0], bh[nt][2]);
                    mma_bf16(acc[mt][2 * nt + 1], al[mt], bh[nt][1], bh[nt][3]);
                    mma_bf16(acc[mt][2 * nt],     ah[mt], bl[nt][0], bl[nt][2]);
                    mma_bf16(acc[mt][2 * nt + 1], ah[mt], bl[nt][1], bl[nt][3]);
                }
        }
        __syncthreads();
    }

    const int g = lane >> 2, tc = lane & 3;
    #pragma unroll
    for (int mt = 0; mt < 2; mt++) {
        #pragma unroll
        for (int nb = 0; nb < 8; nb++) {
            int col = wn * 64 + nb * 8 + tc * 2;
            float b0 = bias2[col], b1 = bias2[col + 1];
            int r0 = m0 + wm * 32 + mt * 16 + g;
            if (r0 < NOUT2)
                *(float2*)(g_x2 + (size_t)r0 * DIM + col) =
                    make_float2(acc[mt][nb][0] + b0, acc[mt][nb][1] + b1);
            int r1 = r0 + 8;
            if (r1 < NOUT2)
                *(float2*)(g_x2 + (size_t)r1 * DIM + col) =
                    make_float2(acc[mt][nb][2] + b0, acc[mt][nb][3] + b1);
        }
    }
}

// ---------------- scorer (HMMA) ----------------
__global__ __launch_bounds__(256) void k_scorer_mma(const int* __restrict__ h_idx, const int* __restrict__ p_idx,
                                                    const float* __restrict__ sb1, const float* __restrict__ sw2,
                                                    const float* __restrict__ sb2, float* __restrict__ out) {
    extern __shared__ char sm[];
    uint32_t* Ah = (uint32_t*)sm;
    uint32_t* Al = (uint32_t*)(sm + TILE_BYTES);
    uint32_t* Bh = (uint32_t*)(sm + 2 * TILE_BYTES);
    uint32_t* Bl = (uint32_t*)(sm + 3 * TILE_BYTES);
    const uint32_t sAh = smem_u32(Ah), sAl = smem_u32(Al), sBh = smem_u32(Bh), sBl = smem_u32(Bl);
    const int tid = threadIdx.x, lane = tid & 31, wid = tid >> 5;
    const int wm = wid & 3, wn = wid >> 2;
    const int lrow = lane & 15, lk = lane >> 4;
    const int pair0 = blockIdx.x * 128;

    float acc[2][8][4];
    #pragma unroll
    for (int i = 0; i < 2; i++)
        #pragma unroll
        for (int j = 0; j < 8; j++)
            #pragma unroll
            for (int c = 0; c < 4; c++) acc[i][j][c] = 0.f;

    for (int c = 0; c < 4; c++) {
        for (int i = tid; i < 128 * 64; i += 256) {
            int row = i >> 6, k2 = i & 63;
            int pr = pair0 + row; if (pr >= NP) pr = NP - 1;
            float2 h = *(const float2*)(g_x2 + (size_t)h_idx[pr] * DIM + k2 * 2);
            float2 p = *(const float2*)(g_x2 + (size_t)(N_HERB + p_idx[pr]) * DIM + k2 * 2);
            float2 f;
            if (c == 0) f = h;
            else if (c == 1) f = p;
            else if (c == 2) f = make_float2(h.x * p.x, h.y * p.y);
            else f = make_float2(fabsf(h.x - p.x), fabsf(h.y - p.y));
            Ah[row * TSTR + k2] = split_pack_hi(f);
            Al[row * TSTR + k2] = split_pack_lo(f);
            Bh[row * TSTR + k2] = g_SW1h[(size_t)row * 256 + c * 64 + k2];
            Bl[row * TSTR + k2] = g_SW1l[(size_t)row * 256 + c * 64 + k2];
        }
        __syncthreads();
        #pragma unroll
        for (int kk8 = 0; kk8 < 8; kk8++) {
            uint32_t ah[2][4], al[2][4], bh[4][4], bl[4][4];
            #pragma unroll
            for (int mt = 0; mt < 2; mt++) {
                uint32_t off = (uint32_t)((wm * 32 + mt * 16 + lrow) * 272 + kk8 * 32 + lk * 16);
                ldm4(ah[mt], sAh + off);
                ldm4(al[mt], sAl + off);
            }
            #pragma unroll
            for (int nt = 0; nt < 4; nt++) {
                uint32_t off = (uint32_t)((wn * 64 + nt * 16 + lrow) * 272 + kk8 * 32 + lk * 16);
                ldm4(bh[nt], sBh + off);
                ldm4(bl[nt], sBl + off);
            }
            #pragma unroll
            for (int mt = 0; mt < 2; mt++)
                #pragma unroll
                for (int nt = 0; nt < 4; nt++) {
                    mma_bf16(acc[mt][2 * nt],     ah[mt], bh[nt][0], bh[nt][2]);
                    mma_bf16(acc[mt][2 * nt + 1], ah[mt], bh[nt][1], bh[nt][3]);
                    mma_bf16(acc[mt][2 * nt],     al[mt], bh[nt][0], bh[nt][2]);
                    mma_bf16(acc[mt][2 * nt + 1], al[mt], bh[nt][1], bh[nt][3]);
                    mma_bf16(acc[mt][2 * nt],     ah[mt], bl[nt][0], bl[nt][2]);
                    mma_bf16(acc[mt][2 * nt + 1], ah[mt], bl[nt][1], bl[nt][3]);
                }
        }
        __syncthreads();
    }

    __syncthreads();
    float* s_part = (float*)sm;              // [128][2]
    const int g = lane >> 2, tc = lane & 3;
    #pragma unroll
    for (int mt = 0; mt < 2; mt++) {
        float s0 = 0.f, s1 = 0.f;
        #pragma unroll
        for (int nb = 0; nb < 8; nb++) {
            int col = wn * 64 + nb * 8 + tc * 2;
            float w0 = sw2[col], w1 = sw2[col + 1];
            float bb0 = sb1[col], bb1 = sb1[col + 1];
            s0 += fmaxf(acc[mt][nb][0] + bb0, 0.f) * w0 + fmaxf(acc[mt][nb][1] + bb1, 0.f) * w1;
            s1 += fmaxf(acc[mt][nb][2] + bb0, 0.f) * w0 + fmaxf(acc[mt][nb][3] + bb1, 0.f) * w1;
        }
        s0 += __shfl_xor_sync(0xffffffff, s0, 1); s0 += __shfl_xor_sync(0xffffffff, s0, 2);
        s1 += __shfl_xor_sync(0xffffffff, s1, 1); s1 += __shfl_xor_sync(0xffffffff, s1, 2);
        if (tc == 0) {
            int r0 = wm * 32 + mt * 16 + g;
            s_part[r0 * 2 + wn] = s0;
            s_part[(r0 + 8) * 2 + wn] = s1;
        }
    }
    __syncthreads();
    if (tid < 128) {
        int pr = pair0 + tid;
        if (pr < NP) out[pr] = s_part[tid * 2] + s_part[tid * 2 + 1] + sb2[0];
    }
}

// ---------------- launch ----------------
extern "C" void kernel_launch(void* const* d_in, const int* in_sizes, int n_in,
                              void* d_out, int out_size) {
    const int*   edge_index = (const int*)d_in[0];
    const int*   edge_type  = (const int*)d_in[1];
    const int*   h_idx      = (const int*)d_in[2];
    const int*   p_idx      = (const int*)d_in[3];
    const float* node_emb   = (const float*)d_in[4];
    const float* basis1 = (const float*)d_in[5];
    const float* comp1  = (const float*)d_in[6];
    const float* root1  = (const float*)d_in[7];
    const float* bias1  = (const float*)d_in[8];
    const float* basis2 = (const float*)d_in[9];
    const float* comp2  = (const float*)d_in[10];
    const float* root2  = (const float*)d_in[11];
    const float* bias2  = (const float*)d_in[12];
    const float* sw1 = (const float*)d_in[13];
    const float* sb1 = (const float*)d_in[14];
    const float* sw2 = (const float*)d_in[15];
    const float* sb2 = (const float*)d_in[16];
    float* out = (float*)d_out;

    const int smem = 4 * TILE_BYTES;   // 139264 B
    cudaFuncSetAttribute(k_gemm1_mma, cudaFuncAttributeMaxDynamicSharedMemorySize, smem);
    cudaFuncSetAttribute(k_gemm2_mma, cudaFuncAttributeMaxDynamicSharedMemorySize, smem);
    cudaFuncSetAttribute(k_scorer_mma, cudaFuncAttributeMaxDynamicSharedMemorySize, smem);

    // weights (independent of graph phases)
    k_build_w1<<<(128 * 448 + 255) / 256, 256>>>(basis1, comp1, root1);
    k_build_w2<<<(128 * 448 + 255) / 256, 256>>>(basis2, comp2, root2);
    k_build_sw1t<<<(128 * 256 + 255) / 256, 256>>>(sw1);

    // CSR: counts -> exclusive scan -> bucket fill
    k_zero_cnt<<<(NSEG1 + 255) / 256, 256>>>();
    k_count<<<(NE + 255) / 256, 256>>>(edge_index, edge_type);
    k_scan_a<<<NBLK, SCAN_BLK>>>();
    k_scan_b<<<1, 512>>>();
    k_scan_c<<<NBLK, SCAN_BLK>>>();
    k_fill<<<(NE + 255) / 256, 256>>>(edge_index, edge_type);

    // layer 1: gather means, then fused transform (+relu)
    k_gather1<<<(NSEG1 * 32 + 255) / 256, 256>>>(node_emb);
    k_gemm1_mma<<<(N_NODES + 127) / 128, 256, smem>>>(node_emb, bias1);

    // layer 2: gather means (only dst < 25000), then fused transform
    k_gather2<<<(NSEG2 * 32 + 255) / 256, 256>>>();
    k_gemm2_mma<<<(NOUT2 + 127) / 128, 256, smem>>>(bias2);

    k_scorer_mma<<<(NP + 127) / 128, 256, smem>>>(h_idx, p_idx, sb1, sw2, sb2, out);
}

// round 6
// speedup vs baseline: 1.6321x; 1.2161x over previous
#include <cuda_runtime.h>
#include <cuda_bf16.h>
#include <cstdint>

#define N_NODES 60000
#define N_HERB  5000
#define NOUT2   25000
#define DIM     128
#define NREL    6
#define NB      30
#define NE      600000
#define NP      40000
#define NSEG1   (N_NODES * NREL)   // 360000
#define NSEG2   (NOUT2 * NREL)     // 150000
#define SCAN_BLK 1024
#define NBLK    ((NSEG1 + SCAN_BLK - 1) / SCAN_BLK)   // 352

// ---------------- scratch ----------------
// split-bf16 aggregates (hi/lo packed bf16x2 per u32): [seg][64]
__device__ uint32_t g_A1h[(size_t)NSEG1 * 64], g_A1l[(size_t)NSEG1 * 64];
__device__ uint32_t g_A2h[(size_t)NSEG2 * 64], g_A2l[(size_t)NSEG2 * 64];
// split node_emb / x1 for GEMM root chunks: [node][64]
__device__ uint32_t g_Eh[(size_t)N_NODES * 64], g_El[(size_t)N_NODES * 64];
__device__ uint32_t g_X1h[(size_t)N_NODES * 64], g_X1l[(size_t)N_NODES * 64];
__device__ float g_x1[(size_t)N_NODES * DIM];     // fp32 for gather2
__device__ float g_x2[(size_t)NOUT2 * DIM];
__device__ int   g_cnt[NSEG1];
__device__ int   g_off[NSEG1 + 1];
__device__ int   g_cursor[NSEG1];
__device__ int   g_esrc[NE];
__device__ int   g_bsum[NBLK], g_bpre[NBLK];
// split bf16 weights, transposed: [out_col][k-pair] (K-major)
__device__ uint32_t g_BT1h[128 * 448], g_BT1l[128 * 448];
__device__ uint32_t g_BT2h[128 * 448], g_BT2l[128 * 448];
__device__ uint32_t g_SW1h[128 * 256], g_SW1l[128 * 256];

// ---------------- helpers ----------------
__device__ __forceinline__ uint32_t smem_u32(const void* p) {
    uint32_t a;
    asm("{ .reg .u64 t; cvta.to.shared.u64 t, %1; cvt.u32.u64 %0, t; }" : "=r"(a) : "l"(p));
    return a;
}
__device__ __forceinline__ void ldm4(uint32_t* r, uint32_t addr) {
    asm volatile("ldmatrix.sync.aligned.m8n8.x4.shared.b16 {%0,%1,%2,%3}, [%4];"
        : "=r"(r[0]), "=r"(r[1]), "=r"(r[2]), "=r"(r[3]) : "r"(addr));
}
__device__ __forceinline__ void mma_bf16(float* d, const uint32_t* a, uint32_t b0, uint32_t b1) {
    asm volatile("mma.sync.aligned.m16n8k16.row.col.f32.bf16.bf16.f32 "
        "{%0,%1,%2,%3}, {%4,%5,%6,%7}, {%8,%9}, {%0,%1,%2,%3};"
        : "+f"(d[0]), "+f"(d[1]), "+f"(d[2]), "+f"(d[3])
        : "r"(a[0]), "r"(a[1]), "r"(a[2]), "r"(a[3]), "r"(b0), "r"(b1));
}
__device__ __forceinline__ uint32_t split_pack_hi(float2 f) {
    __nv_bfloat162 h;
    h.x = __float2bfloat16_rn(f.x); h.y = __float2bfloat16_rn(f.y);
    return *(uint32_t*)&h;
}
__device__ __forceinline__ uint32_t split_pack_lo(float2 f) {
    __nv_bfloat16 hx = __float2bfloat16_rn(f.x), hy = __float2bfloat16_rn(f.y);
    __nv_bfloat162 l;
    l.x = __float2bfloat16_rn(f.x - __bfloat162float(hx));
    l.y = __float2bfloat16_rn(f.y - __bfloat162float(hy));
    return *(uint32_t*)&l;
}
__device__ __forceinline__ void cpa16(uint32_t saddr, const void* g) {
    asm volatile("cp.async.cg.shared.global [%0], [%1], 16;" :: "r"(saddr), "l"(g));
}
#define CP_COMMIT() asm volatile("cp.async.commit_group;" ::: "memory")
#define CP_WAIT(n)  asm volatile("cp.async.wait_group %0;" :: "n"(n) : "memory")

// pipelined GEMM tile: 128 rows x 32 u32, padded stride 36 u32 (144 B, conflict-free ldmatrix)
#define PSTR 36
#define PTILE (128 * PSTR * 4)    // 18432 B
#define PSMEM (8 * PTILE)         // 147456 B (2 stages x 4 tiles)
// scorer (round-5 geometry)
#define TSTR 68
#define TILE_BYTES (128 * TSTR * 4)   // 34816

// ---------------- weight / emb build ----------------
__global__ void k_build_w1(const float* __restrict__ basis, const float* __restrict__ comp,
                           const float* __restrict__ root) {
    int idx = blockIdx.x * blockDim.x + threadIdx.x;
    if (idx >= 128 * 448) return;
    int o = idx / 448, j = idx % 448, k0 = j * 2;
    float w0, w1;
    if (k0 < 768) {
        int r = k0 >> 7, d0 = k0 & 127;
        w0 = 0.f; w1 = 0.f;
        #pragma unroll
        for (int b = 0; b < NB; b++) {
            float cc = comp[r * NB + b];
            w0 += cc * basis[b * 16384 + d0 * 128 + o];
            w1 += cc * basis[b * 16384 + (d0 + 1) * 128 + o];
        }
    } else {
        int d0 = k0 - 768;
        w0 = root[d0 * 128 + o]; w1 = root[(d0 + 1) * 128 + o];
    }
    float2 f = make_float2(w0, w1);
    g_BT1h[idx] = split_pack_hi(f);
    g_BT1l[idx] = split_pack_lo(f);
}
__global__ void k_build_w2(const float* __restrict__ basis, const float* __restrict__ comp,
                           const float* __restrict__ root) {
    int idx = blockIdx.x * blockDim.x + threadIdx.x;
    if (idx >= 128 * 448) return;
    int o = idx / 448, j = idx % 448, k0 = j * 2;
    float w0, w1;
    if (k0 < 768) {
        int r = k0 >> 7, d0 = k0 & 127;
        w0 = 0.f; w1 = 0.f;
        #pragma unroll
        for (int b = 0; b < NB; b++) {
            float cc = comp[r * NB + b];
            w0 += cc * basis[b * 16384 + d0 * 128 + o];
            w1 += cc * basis[b * 16384 + (d0 + 1) * 128 + o];
        }
    } else {
        int d0 = k0 - 768;
        w0 = root[d0 * 128 + o]; w1 = root[(d0 + 1) * 128 + o];
    }
    float2 f = make_float2(w0, w1);
    g_BT2h[idx] = split_pack_hi(f);
    g_BT2l[idx] = split_pack_lo(f);
}
__global__ void k_build_sw1t(const float* __restrict__ sw1) {
    int idx = blockIdx.x * blockDim.x + threadIdx.x;
    if (idx >= 128 * 256) return;
    int o = idx >> 8, j = idx & 255, k0 = j * 2;
    float2 f = make_float2(sw1[k0 * 128 + o], sw1[(k0 + 1) * 128 + o]);
    g_SW1h[idx] = split_pack_hi(f);
    g_SW1l[idx] = split_pack_lo(f);
}
__global__ void k_build_emb(const float* __restrict__ X) {
    int idx = blockIdx.x * blockDim.x + threadIdx.x;
    if (idx >= N_NODES * 64) return;
    float2 f = ((const float2*)X)[idx];
    g_Eh[idx] = split_pack_hi(f);
    g_El[idx] = split_pack_lo(f);
}

// ---------------- CSR build ----------------
__global__ void k_zero_cnt() {
    int i = blockIdx.x * blockDim.x + threadIdx.x;
    if (i < NSEG1) g_cnt[i] = 0;
}
__global__ void k_count(const int* __restrict__ ei, const int* __restrict__ et) {
    int e = blockIdx.x * blockDim.x + threadIdx.x;
    if (e < NE) atomicAdd(&g_cnt[ei[NE + e] * NREL + et[e]], 1);
}
__global__ __launch_bounds__(SCAN_BLK) void k_scan_a() {
    __shared__ int sm[SCAN_BLK];
    int t = threadIdx.x;
    int gid = blockIdx.x * SCAN_BLK + t;
    int v = (gid < NSEG1) ? g_cnt[gid] : 0;
    sm[t] = v;
    __syncthreads();
    for (int d = 1; d < SCAN_BLK; d <<= 1) {
        int x = (t >= d) ? sm[t - d] : 0;
        __syncthreads();
        sm[t] += x;
        __syncthreads();
    }
    if (gid < NSEG1) g_off[gid] = sm[t] - v;
    if (t == SCAN_BLK - 1) g_bsum[blockIdx.x] = sm[t];
}
__global__ __launch_bounds__(512) void k_scan_b() {
    __shared__ int sm[512];
    int t = threadIdx.x;
    int v = (t < NBLK) ? g_bsum[t] : 0;
    sm[t] = v;
    __syncthreads();
    for (int d = 1; d < 512; d <<= 1) {
        int x = (t >= d) ? sm[t - d] : 0;
        __syncthreads();
        sm[t] += x;
        __syncthreads();
    }
    if (t < NBLK) g_bpre[t] = sm[t] - v;
}
__global__ __launch_bounds__(SCAN_BLK) void k_scan_c() {
    int gid = blockIdx.x * SCAN_BLK + threadIdx.x;
    if (gid < NSEG1) {
        int o = g_off[gid] + g_bpre[blockIdx.x];
        g_off[gid] = o;
        g_cursor[gid] = o;
    }
    if (gid == 0) g_off[NSEG1] = NE;
}
__global__ void k_fill(const int* __restrict__ ei, const int* __restrict__ et) {
    int e = blockIdx.x * blockDim.x + threadIdx.x;
    if (e < NE) {
        int seg = ei[NE + e] * NREL + et[e];
        int pos = atomicAdd(&g_cursor[seg], 1);
        g_esrc[pos] = ei[e];
    }
}

// ---------------- gathers: mean over segment -> split bf16 hi/lo ----------------
__global__ __launch_bounds__(256) void k_gather1(const float* __restrict__ X) {
    int w = (int)((blockIdx.x * 256u + threadIdx.x) >> 5);
    if (w >= NSEG1) return;
    int lane = threadIdx.x & 31;
    int s0 = g_off[w], s1 = g_off[w + 1];
    float4 acc = make_float4(0.f, 0.f, 0.f, 0.f);
    for (int e = s0; e < s1; e++) {
        const float4 v = *(const float4*)(X + (size_t)g_esrc[e] * DIM + lane * 4);
        acc.x += v.x; acc.y += v.y; acc.z += v.z; acc.w += v.w;
    }
    float sc = (s1 > s0) ? 1.f / (float)(s1 - s0) : 0.f;
    float2 f01 = make_float2(acc.x * sc, acc.y * sc);
    float2 f23 = make_float2(acc.z * sc, acc.w * sc);
    size_t base = (size_t)w * 64 + lane * 2;
    *(uint2*)(g_A1h + base) = make_uint2(split_pack_hi(f01), split_pack_hi(f23));
    *(uint2*)(g_A1l + base) = make_uint2(split_pack_lo(f01), split_pack_lo(f23));
}
__global__ __launch_bounds__(256) void k_gather2() {
    int w = (int)((blockIdx.x * 256u + threadIdx.x) >> 5);
    if (w >= NSEG2) return;
    int lane = threadIdx.x & 31;
    int s0 = g_off[w], s1 = g_off[w + 1];
    float4 acc = make_float4(0.f, 0.f, 0.f, 0.f);
    for (int e = s0; e < s1; e++) {
        const float4 v = *(const float4*)(g_x1 + (size_t)g_esrc[e] * DIM + lane * 4);
        acc.x += v.x; acc.y += v.y; acc.z += v.z; acc.w += v.w;
    }
    float sc = (s1 > s0) ? 1.f / (float)(s1 - s0) : 0.f;
    float2 f01 = make_float2(acc.x * sc, acc.y * sc);
    float2 f23 = make_float2(acc.z * sc, acc.w * sc);
    size_t base = (size_t)w * 64 + lane * 2;
    *(uint2*)(g_A2h + base) = make_uint2(split_pack_hi(f01), split_pack_hi(f23));
    *(uint2*)(g_A2l + base) = make_uint2(split_pack_lo(f01), split_pack_lo(f23));
}

// ---------------- pipelined HMMA GEMM core (macro-shared by both layers) ----------------
// A source per chunk c (0..13): c<12 -> agg[(grow*6 + c/2)*64 + (c&1)*32], else root[grow*64 + (c-12)*32]
#define STAGE_CHUNK(c_, s_, AGGH, AGGL, ROOTH, ROOTL, BTH, BTL, NLIM)                         \
    do {                                                                                      \
        int cc = (c_);                                                                        \
        uint32_t sb0 = sbase + (uint32_t)((s_) * 4) * PTILE;                                  \
        _Pragma("unroll")                                                                     \
        for (int k = 0; k < 4; k++) {                                                         \
            int idx = tid + k * 256;                                                          \
            int row = idx >> 3, c16 = idx & 7;                                                \
            int grow = m0 + row; if (grow >= (NLIM)) grow = (NLIM) - 1;                       \
            const uint32_t *srch, *srcl;                                                      \
            if (cc < 12) {                                                                    \
                size_t sgb = ((size_t)grow * 6 + (cc >> 1)) * 64 + (cc & 1) * 32;             \
                srch = (AGGH) + sgb; srcl = (AGGL) + sgb;                                     \
            } else {                                                                          \
                size_t sgb = (size_t)grow * 64 + (cc - 12) * 32;                              \
                srch = (ROOTH) + sgb; srcl = (ROOTL) + sgb;                                   \
            }                                                                                 \
            uint32_t so = (uint32_t)(row * 144 + c16 * 16);                                   \
            cpa16(sb0 + 0 * PTILE + so, srch + c16 * 4);                                      \
            cpa16(sb0 + 1 * PTILE + so, srcl + c16 * 4);                                      \
            const uint32_t* bh = (BTH) + (size_t)row * 448 + cc * 32;                         \
            const uint32_t* bl = (BTL) + (size_t)row * 448 + cc * 32;                         \
            cpa16(sb0 + 2 * PTILE + so, bh + c16 * 4);                                        \
            cpa16(sb0 + 3 * PTILE + so, bl + c16 * 4);                                        \
        }                                                                                     \
        CP_COMMIT();                                                                          \
    } while (0)

#define MMA_CHUNK(s_)                                                                         \
    do {                                                                                      \
        uint32_t sb0 = sbase + (uint32_t)((s_) * 4) * PTILE;                                  \
        _Pragma("unroll")                                                                     \
        for (int kk = 0; kk < 4; kk++) {                                                      \
            uint32_t ah[2][4], al[2][4], bh[4][4], bl[4][4];                                  \
            _Pragma("unroll")                                                                 \
            for (int mt = 0; mt < 2; mt++) {                                                  \
                uint32_t off = (uint32_t)((wm * 32 + mt * 16 + lrow) * 144 + kk * 32 + lk * 16); \
                ldm4(ah[mt], sb0 + 0 * PTILE + off);                                          \
                ldm4(al[mt], sb0 + 1 * PTILE + off);                                          \
            }                                                                                 \
            _Pragma("unroll")                                                                 \
            for (int nt = 0; nt < 4; nt++) {                                                  \
                uint32_t off = (uint32_t)((wn * 64 + nt * 16 + lrow) * 144 + kk * 32 + lk * 16); \
                ldm4(bh[nt], sb0 + 2 * PTILE + off);                                          \
                ldm4(bl[nt], sb0 + 3 * PTILE + off);                                          \
            }                                                                                 \
            _Pragma("unroll")                                                                 \
            for (int mt = 0; mt < 2; mt++)                                                    \
                _Pragma("unroll")                                                             \
                for (int nt = 0; nt < 4; nt++) {                                              \
                    mma_bf16(acc[mt][2 * nt],     ah[mt], bh[nt][0], bh[nt][2]);              \
                    mma_bf16(acc[mt][2 * nt + 1], ah[mt], bh[nt][1], bh[nt][3]);              \
                    mma_bf16(acc[mt][2 * nt],     al[mt], bh[nt][0], bh[nt][2]);              \
                    mma_bf16(acc[mt][2 * nt + 1], al[mt], bh[nt][1], bh[nt][3]);              \
                    mma_bf16(acc[mt][2 * nt],     ah[mt], bl[nt][0], bl[nt][2]);              \
                    mma_bf16(acc[mt][2 * nt + 1], ah[mt], bl[nt][1], bl[nt][3]);              \
                }                                                                             \
        }                                                                                     \
    } while (0)

// GEMM1: x1 = relu([agg1 | emb] @ B1' + bias1); writes fp32 x1 + split X1
__global__ __launch_bounds__(256) void k_gemm1_p(const float* __restrict__ bias1) {
    extern __shared__ char sm[];
    const uint32_t sbase = smem_u32(sm);
    const int tid = threadIdx.x, lane = tid & 31, wid = tid >> 5;
    const int wm = wid & 3, wn = wid >> 2;
    const int lrow = lane & 15, lk = lane >> 4;
    const int m0 = blockIdx.x * 128;

    float acc[2][8][4];
    #pragma unroll
    for (int i = 0; i < 2; i++)
        #pragma unroll
        for (int j = 0; j < 8; j++)
            #pragma unroll
            for (int c = 0; c < 4; c++) acc[i][j][c] = 0.f;

    STAGE_CHUNK(0, 0, g_A1h, g_A1l, g_Eh, g_El, g_BT1h, g_BT1l, N_NODES);
    for (int c = 0; c < 14; c++) {
        int s = c & 1;
        if (c < 13) {
            STAGE_CHUNK(c + 1, s ^ 1, g_A1h, g_A1l, g_Eh, g_El, g_BT1h, g_BT1l, N_NODES);
            CP_WAIT(1);
        } else {
            CP_WAIT(0);
        }
        __syncthreads();
        MMA_CHUNK(s);
        __syncthreads();
    }

    const int g = lane >> 2, tc = lane & 3;
    #pragma unroll
    for (int mt = 0; mt < 2; mt++) {
        #pragma unroll
        for (int nb = 0; nb < 8; nb++) {
            int col = wn * 64 + nb * 8 + tc * 2;
            float b0 = bias1[col], b1 = bias1[col + 1];
            int pi = col >> 1;
            int r0 = m0 + wm * 32 + mt * 16 + g;
            if (r0 < N_NODES) {
                float2 v = make_float2(fmaxf(acc[mt][nb][0] + b0, 0.f), fmaxf(acc[mt][nb][1] + b1, 0.f));
                *(float2*)(g_x1 + (size_t)r0 * DIM + col) = v;
                g_X1h[(size_t)r0 * 64 + pi] = split_pack_hi(v);
                g_X1l[(size_t)r0 * 64 + pi] = split_pack_lo(v);
            }
            int r1 = r0 + 8;
            if (r1 < N_NODES) {
                float2 v = make_float2(fmaxf(acc[mt][nb][2] + b0, 0.f), fmaxf(acc[mt][nb][3] + b1, 0.f));
                *(float2*)(g_x1 + (size_t)r1 * DIM + col) = v;
                g_X1h[(size_t)r1 * 64 + pi] = split_pack_hi(v);
                g_X1l[(size_t)r1 * 64 + pi] = split_pack_lo(v);
            }
        }
    }
}

// GEMM2: x2 = [agg2 | x1] @ B2' + bias2
__global__ __launch_bounds__(256) void k_gemm2_p(const float* __restrict__ bias2) {
    extern __shared__ char sm[];
    const uint32_t sbase = smem_u32(sm);
    const int tid = threadIdx.x, lane = tid & 31, wid = tid >> 5;
    const int wm = wid & 3, wn = wid >> 2;
    const int lrow = lane & 15, lk = lane >> 4;
    const int m0 = blockIdx.x * 128;

    float acc[2][8][4];
    #pragma unroll
    for (int i = 0; i < 2; i++)
        #pragma unroll
        for (int j = 0; j < 8; j++)
            #pragma unroll
            for (int c = 0; c < 4; c++) acc[i][j][c] = 0.f;

    STAGE_CHUNK(0, 0, g_A2h, g_A2l, g_X1h, g_X1l, g_BT2h, g_BT2l, NOUT2);
    for (int c = 0; c < 14; c++) {
        int s = c & 1;
        if (c < 13) {
            STAGE_CHUNK(c + 1, s ^ 1, g_A2h, g_A2l, g_X1h, g_X1l, g_BT2h, g_BT2l, NOUT2);
            CP_WAIT(1);
        } else {
            CP_WAIT(0);
        }
        __syncthreads();
        MMA_CHUNK(s);
        __syncthreads();
    }

    const int g = lane >> 2, tc = lane & 3;
    #pragma unroll
    for (int mt = 0; mt < 2; mt++) {
        #pragma unroll
        for (int nb = 0; nb < 8; nb++) {
            int col = wn * 64 + nb * 8 + tc * 2;
            float b0 = bias2[col], b1 = bias2[col + 1];
            int r0 = m0 + wm * 32 + mt * 16 + g;
            if (r0 < NOUT2)
                *(float2*)(g_x2 + (size_t)r0 * DIM + col) =
                    make_float2(acc[mt][nb][0] + b0, acc[mt][nb][1] + b1);
            int r1 = r0 + 8;
            if (r1 < NOUT2)
                *(float2*)(g_x2 + (size_t)r1 * DIM + col) =
                    make_float2(acc[mt][nb][2] + b0, acc[mt][nb][3] + b1);
        }
    }
}

// ---------------- scorer (HMMA, round-5 proven) ----------------
__global__ __launch_bounds__(256) void k_scorer_mma(const int* __restrict__ h_idx, const int* __restrict__ p_idx,
                                                    const float* __restrict__ sb1, const float* __restrict__ sw2,
                                                    const float* __restrict__ sb2, float* __restrict__ out) {
    extern __shared__ char sm[];
    uint32_t* Ah = (uint32_t*)sm;
    uint32_t* Al = (uint32_t*)(sm + TILE_BYTES);
    uint32_t* Bh = (uint32_t*)(sm + 2 * TILE_BYTES);
    uint32_t* Bl = (uint32_t*)(sm + 3 * TILE_BYTES);
    const uint32_t sAh = smem_u32(Ah), sAl = smem_u32(Al), sBh = smem_u32(Bh), sBl = smem_u32(Bl);
    const int tid = threadIdx.x, lane = tid & 31, wid = tid >> 5;
    const int wm = wid & 3, wn = wid >> 2;
    const int lrow = lane & 15, lk = lane >> 4;
    const int pair0 = blockIdx.x * 128;

    float acc[2][8][4];
    #pragma unroll
    for (int i = 0; i < 2; i++)
        #pragma unroll
        for (int j = 0; j < 8; j++)
            #pragma unroll
            for (int c = 0; c < 4; c++) acc[i][j][c] = 0.f;

    for (int c = 0; c < 4; c++) {
        for (int i = tid; i < 128 * 64; i += 256) {
            int row = i >> 6, k2 = i & 63;
            int pr = pair0 + row; if (pr >= NP) pr = NP - 1;
            float2 h = *(const float2*)(g_x2 + (size_t)h_idx[pr] * DIM + k2 * 2);
            float2 p = *(const float2*)(g_x2 + (size_t)(N_HERB + p_idx[pr]) * DIM + k2 * 2);
            float2 f;
            if (c == 0) f = h;
            else if (c == 1) f = p;
            else if (c == 2) f = make_float2(h.x * p.x, h.y * p.y);
            else f = make_float2(fabsf(h.x - p.x), fabsf(h.y - p.y));
            Ah[row * TSTR + k2] = split_pack_hi(f);
            Al[row * TSTR + k2] = split_pack_lo(f);
            Bh[row * TSTR + k2] = g_SW1h[(size_t)row * 256 + c * 64 + k2];
            Bl[row * TSTR + k2] = g_SW1l[(size_t)row * 256 + c * 64 + k2];
        }
        __syncthreads();
        #pragma unroll
        for (int kk8 = 0; kk8 < 8; kk8++) {
            uint32_t ah[2][4], al[2][4], bh[4][4], bl[4][4];
            #pragma unroll
            for (int mt = 0; mt < 2; mt++) {
                uint32_t off = (uint32_t)((wm * 32 + mt * 16 + lrow) * 272 + kk8 * 32 + lk * 16);
                ldm4(ah[mt], sAh + off);
                ldm4(al[mt], sAl + off);
            }
            #pragma unroll
            for (int nt = 0; nt < 4; nt++) {
                uint32_t off = (uint32_t)((wn * 64 + nt * 16 + lrow) * 272 + kk8 * 32 + lk * 16);
                ldm4(bh[nt], sBh + off);
                ldm4(bl[nt], sBl + off);
            }
            #pragma unroll
            for (int mt = 0; mt < 2; mt++)
                #pragma unroll
                for (int nt = 0; nt < 4; nt++) {
                    mma_bf16(acc[mt][2 * nt],     ah[mt], bh[nt][0], bh[nt][2]);
                    mma_bf16(acc[mt][2 * nt + 1], ah[mt], bh[nt][1], bh[nt][3]);
                    mma_bf16(acc[mt][2 * nt],     al[mt], bh[nt][0], bh[nt][2]);
                    mma_bf16(acc[mt][2 * nt + 1], al[mt], bh[nt][1], bh[nt][3]);
                    mma_bf16(acc[mt][2 * nt],     ah[mt], bl[nt][0], bl[nt][2]);
                    mma_bf16(acc[mt][2 * nt + 1], ah[mt], bl[nt][1], bl[nt][3]);
                }
        }
        __syncthreads();
    }

    __syncthreads();
    float* s_part = (float*)sm;              // [128][2]
    const int g = lane >> 2, tc = lane & 3;
    #pragma unroll
    for (int mt = 0; mt < 2; mt++) {
        float s0 = 0.f, s1 = 0.f;
        #pragma unroll
        for (int nb = 0; nb < 8; nb++) {
            int col = wn * 64 + nb * 8 + tc * 2;
            float w0 = sw2[col], w1 = sw2[col + 1];
            float bb0 = sb1[col], bb1 = sb1[col + 1];
            s0 += fmaxf(acc[mt][nb][0] + bb0, 0.f) * w0 + fmaxf(acc[mt][nb][1] + bb1, 0.f) * w1;
            s1 += fmaxf(acc[mt][nb][2] + bb0, 0.f) * w0 + fmaxf(acc[mt][nb][3] + bb1, 0.f) * w1;
        }
        s0 += __shfl_xor_sync(0xffffffff, s0, 1); s0 += __shfl_xor_sync(0xffffffff, s0, 2);
        s1 += __shfl_xor_sync(0xffffffff, s1, 1); s1 += __shfl_xor_sync(0xffffffff, s1, 2);
        if (tc == 0) {
            int r0 = wm * 32 + mt * 16 + g;
            s_part[r0 * 2 + wn] = s0;
            s_part[(r0 + 8) * 2 + wn] = s1;
        }
    }
    __syncthreads();
    if (tid < 128) {
        int pr = pair0 + tid;
        if (pr < NP) out[pr] = s_part[tid * 2] + s_part[tid * 2 + 1] + sb2[0];
    }
}

// ---------------- launch ----------------
extern "C" void kernel_launch(void* const* d_in, const int* in_sizes, int n_in,
                              void* d_out, int out_size) {
    const int*   edge_index = (const int*)d_in[0];
    const int*   edge_type  = (const int*)d_in[1];
    const int*   h_idx      = (const int*)d_in[2];
    const int*   p_idx      = (const int*)d_in[3];
    const float* node_emb   = (const float*)d_in[4];
    const float* basis1 = (const float*)d_in[5];
    const float* comp1  = (const float*)d_in[6];
    const float* root1  = (const float*)d_in[7];
    const float* bias1  = (const float*)d_in[8];
    const float* basis2 = (const float*)d_in[9];
    const float* comp2  = (const float*)d_in[10];
    const float* root2  = (const float*)d_in[11];
    const float* bias2  = (const float*)d_in[12];
    const float* sw1 = (const float*)d_in[13];
    const float* sb1 = (const float*)d_in[14];
    const float* sw2 = (const float*)d_in[15];
    const float* sb2 = (const float*)d_in[16];
    float* out = (float*)d_out;

    cudaFuncSetAttribute(k_gemm1_p, cudaFuncAttributeMaxDynamicSharedMemorySize, PSMEM);
    cudaFuncSetAttribute(k_gemm2_p, cudaFuncAttributeMaxDynamicSharedMemorySize, PSMEM);
    cudaFuncSetAttribute(k_scorer_mma, cudaFuncAttributeMaxDynamicSharedMemorySize, 4 * TILE_BYTES);

    // weights + emb split (independent)
    k_build_w1<<<(128 * 448 + 255) / 256, 256>>>(basis1, comp1, root1);
    k_build_w2<<<(128 * 448 + 255) / 256, 256>>>(basis2, comp2, root2);
    k_build_sw1t<<<(128 * 256 + 255) / 256, 256>>>(sw1);
    k_build_emb<<<(N_NODES * 64 + 255) / 256, 256>>>(node_emb);

    // CSR: counts -> exclusive scan -> bucket fill
    k_zero_cnt<<<(NSEG1 + 255) / 256, 256>>>();
    k_count<<<(NE + 255) / 256, 256>>>(edge_index, edge_type);
    k_scan_a<<<NBLK, SCAN_BLK>>>();
    k_scan_b<<<1, 512>>>();
    k_scan_c<<<NBLK, SCAN_BLK>>>();
    k_fill<<<(NE + 255) / 256, 256>>>(edge_index, edge_type);

    // layer 1
    k_gather1<<<(NSEG1 * 32 + 255) / 256, 256>>>(node_emb);
    k_gemm1_p<<<(N_NODES + 127) / 128, 256, PSMEM>>>(bias1);

    // layer 2
    k_gather2<<<(NSEG2 * 32 + 255) / 256, 256>>>();
    k_gemm2_p<<<(NOUT2 + 127) / 128, 256, PSMEM>>>(bias2);

    k_scorer_mma<<<(NP + 127) / 128, 256, 4 * TILE_BYTES>>>(h_idx, p_idx, sb1, sw2, sb2, out);
}

// round 7
// speedup vs baseline: 1.6425x; 1.0064x over previous
#include <cuda_runtime.h>
#include <cuda_bf16.h>
#include <cstdint>

#define N_NODES 60000
#define N_HERB  5000
#define NOUT2   25000
#define DIM     128
#define NREL    6
#define NB      30
#define NE      600000
#define NP      40000
#define NSEG1   (N_NODES * NREL)   // 360000
#define NSEG2   (NOUT2 * NREL)     // 150000
#define SCAN_BLK 1024
#define NBLK    ((NSEG1 + SCAN_BLK - 1) / SCAN_BLK)   // 352

// ---------------- scratch ----------------
__device__ uint32_t g_A1h[(size_t)NSEG1 * 64], g_A1l[(size_t)NSEG1 * 64];
__device__ uint32_t g_A2h[(size_t)NSEG2 * 64], g_A2l[(size_t)NSEG2 * 64];
__device__ uint32_t g_Eh[(size_t)N_NODES * 64], g_El[(size_t)N_NODES * 64];
__device__ uint32_t g_X1h[(size_t)N_NODES * 64], g_X1l[(size_t)N_NODES * 64];
__device__ float g_x1[(size_t)N_NODES * DIM];
__device__ float g_x2[(size_t)NOUT2 * DIM];
__device__ int   g_cnt[NSEG1];
__device__ int   g_off[NSEG1 + 1];
__device__ int   g_cursor[NSEG1];
__device__ int   g_esrc[NE];
__device__ int   g_bsum[NBLK], g_bpre[NBLK];
__device__ uint32_t g_BT1h[128 * 448], g_BT1l[128 * 448];
__device__ uint32_t g_BT2h[128 * 448], g_BT2l[128 * 448];
__device__ uint32_t g_SW1h[128 * 256], g_SW1l[128 * 256];

// ---------------- helpers ----------------
__device__ __forceinline__ uint32_t smem_u32(const void* p) {
    uint32_t a;
    asm("{ .reg .u64 t; cvta.to.shared.u64 t, %1; cvt.u32.u64 %0, t; }" : "=r"(a) : "l"(p));
    return a;
}
__device__ __forceinline__ void ldm4(uint32_t* r, uint32_t addr) {
    asm volatile("ldmatrix.sync.aligned.m8n8.x4.shared.b16 {%0,%1,%2,%3}, [%4];"
        : "=r"(r[0]), "=r"(r[1]), "=r"(r[2]), "=r"(r[3]) : "r"(addr));
}
__device__ __forceinline__ void mma_bf16(float* d, const uint32_t* a, uint32_t b0, uint32_t b1) {
    asm volatile("mma.sync.aligned.m16n8k16.row.col.f32.bf16.bf16.f32 "
        "{%0,%1,%2,%3}, {%4,%5,%6,%7}, {%8,%9}, {%0,%1,%2,%3};"
        : "+f"(d[0]), "+f"(d[1]), "+f"(d[2]), "+f"(d[3])
        : "r"(a[0]), "r"(a[1]), "r"(a[2]), "r"(a[3]), "r"(b0), "r"(b1));
}
__device__ __forceinline__ uint32_t split_pack_hi(float2 f) {
    __nv_bfloat162 h;
    h.x = __float2bfloat16_rn(f.x); h.y = __float2bfloat16_rn(f.y);
    return *(uint32_t*)&h;
}
__device__ __forceinline__ uint32_t split_pack_lo(float2 f) {
    __nv_bfloat16 hx = __float2bfloat16_rn(f.x), hy = __float2bfloat16_rn(f.y);
    __nv_bfloat162 l;
    l.x = __float2bfloat16_rn(f.x - __bfloat162float(hx));
    l.y = __float2bfloat16_rn(f.y - __bfloat162float(hy));
    return *(uint32_t*)&l;
}
__device__ __forceinline__ void cpa16(uint32_t saddr, const void* g) {
    asm volatile("cp.async.cg.shared.global [%0], [%1], 16;" :: "r"(saddr), "l"(g));
}
#define CP_COMMIT() asm volatile("cp.async.commit_group;" ::: "memory")
#define CP_WAIT(n)  asm volatile("cp.async.wait_group %0;" :: "n"(n) : "memory")

// pipelined GEMM tile: 128 rows x 16 u32 (K=32 bf16), padded stride 20 u32 (80 B)
#define PSTR 20
#define PTILE (128 * PSTR * 4)    // 10240 B
#define PSMEM (8 * PTILE)         // 81920 B (2 stages x 4 tiles) -> 2 CTAs/SM
// scorer geometry (round-5 proven)
#define TSTR 68
#define TILE_BYTES (128 * TSTR * 4)   // 34816

// ---------------- weight / emb build ----------------
__global__ void k_build_w1(const float* __restrict__ basis, const float* __restrict__ comp,
                           const float* __restrict__ root) {
    int idx = blockIdx.x * blockDim.x + threadIdx.x;
    if (idx >= 128 * 448) return;
    int o = idx / 448, j = idx % 448, k0 = j * 2;
    float w0, w1;
    if (k0 < 768) {
        int r = k0 >> 7, d0 = k0 & 127;
        w0 = 0.f; w1 = 0.f;
        #pragma unroll
        for (int b = 0; b < NB; b++) {
            float cc = comp[r * NB + b];
            w0 += cc * basis[b * 16384 + d0 * 128 + o];
            w1 += cc * basis[b * 16384 + (d0 + 1) * 128 + o];
        }
    } else {
        int d0 = k0 - 768;
        w0 = root[d0 * 128 + o]; w1 = root[(d0 + 1) * 128 + o];
    }
    float2 f = make_float2(w0, w1);
    g_BT1h[idx] = split_pack_hi(f);
    g_BT1l[idx] = split_pack_lo(f);
}
__global__ void k_build_w2(const float* __restrict__ basis, const float* __restrict__ comp,
                           const float* __restrict__ root) {
    int idx = blockIdx.x * blockDim.x + threadIdx.x;
    if (idx >= 128 * 448) return;
    int o = idx / 448, j = idx % 448, k0 = j * 2;
    float w0, w1;
    if (k0 < 768) {
        int r = k0 >> 7, d0 = k0 & 127;
        w0 = 0.f; w1 = 0.f;
        #pragma unroll
        for (int b = 0; b < NB; b++) {
            float cc = comp[r * NB + b];
            w0 += cc * basis[b * 16384 + d0 * 128 + o];
            w1 += cc * basis[b * 16384 + (d0 + 1) * 128 + o];
        }
    } else {
        int d0 = k0 - 768;
        w0 = root[d0 * 128 + o]; w1 = root[(d0 + 1) * 128 + o];
    }
    float2 f = make_float2(w0, w1);
    g_BT2h[idx] = split_pack_hi(f);
    g_BT2l[idx] = split_pack_lo(f);
}
__global__ void k_build_sw1t(const float* __restrict__ sw1) {
    int idx = blockIdx.x * blockDim.x + threadIdx.x;
    if (idx >= 128 * 256) return;
    int o = idx >> 8, j = idx & 255, k0 = j * 2;
    float2 f = make_float2(sw1[k0 * 128 + o], sw1[(k0 + 1) * 128 + o]);
    g_SW1h[idx] = split_pack_hi(f);
    g_SW1l[idx] = split_pack_lo(f);
}
__global__ void k_build_emb(const float* __restrict__ X) {
    int idx = blockIdx.x * blockDim.x + threadIdx.x;
    if (idx >= N_NODES * 64) return;
    float2 f = ((const float2*)X)[idx];
    g_Eh[idx] = split_pack_hi(f);
    g_El[idx] = split_pack_lo(f);
}

// ---------------- CSR build ----------------
__global__ void k_zero_cnt() {
    int i = blockIdx.x * blockDim.x + threadIdx.x;
    if (i < NSEG1) g_cnt[i] = 0;
}
__global__ void k_count(const int* __restrict__ ei, const int* __restrict__ et) {
    int e = blockIdx.x * blockDim.x + threadIdx.x;
    if (e < NE) atomicAdd(&g_cnt[ei[NE + e] * NREL + et[e]], 1);
}
__global__ __launch_bounds__(SCAN_BLK) void k_scan_a() {
    __shared__ int sm[SCAN_BLK];
    int t = threadIdx.x;
    int gid = blockIdx.x * SCAN_BLK + t;
    int v = (gid < NSEG1) ? g_cnt[gid] : 0;
    sm[t] = v;
    __syncthreads();
    for (int d = 1; d < SCAN_BLK; d <<= 1) {
        int x = (t >= d) ? sm[t - d] : 0;
        __syncthreads();
        sm[t] += x;
        __syncthreads();
    }
    if (gid < NSEG1) g_off[gid] = sm[t] - v;
    if (t == SCAN_BLK - 1) g_bsum[blockIdx.x] = sm[t];
}
__global__ __launch_bounds__(512) void k_scan_b() {
    __shared__ int sm[512];
    int t = threadIdx.x;
    int v = (t < NBLK) ? g_bsum[t] : 0;
    sm[t] = v;
    __syncthreads();
    for (int d = 1; d < 512; d <<= 1) {
        int x = (t >= d) ? sm[t - d] : 0;
        __syncthreads();
        sm[t] += x;
        __syncthreads();
    }
    if (t < NBLK) g_bpre[t] = sm[t] - v;
}
__global__ __launch_bounds__(SCAN_BLK) void k_scan_c() {
    int gid = blockIdx.x * SCAN_BLK + threadIdx.x;
    if (gid < NSEG1) {
        int o = g_off[gid] + g_bpre[blockIdx.x];
        g_off[gid] = o;
        g_cursor[gid] = o;
    }
    if (gid == 0) g_off[NSEG1] = NE;
}
__global__ void k_fill(const int* __restrict__ ei, const int* __restrict__ et) {
    int e = blockIdx.x * blockDim.x + threadIdx.x;
    if (e < NE) {
        int seg = ei[NE + e] * NREL + et[e];
        int pos = atomicAdd(&g_cursor[seg], 1);
        g_esrc[pos] = ei[e];
    }
}

// ---------------- gathers ----------------
__global__ __launch_bounds__(256) void k_gather1(const float* __restrict__ X) {
    int w = (int)((blockIdx.x * 256u + threadIdx.x) >> 5);
    if (w >= NSEG1) return;
    int lane = threadIdx.x & 31;
    int s0 = g_off[w], s1 = g_off[w + 1];
    float4 acc = make_float4(0.f, 0.f, 0.f, 0.f);
    for (int e = s0; e < s1; e++) {
        const float4 v = *(const float4*)(X + (size_t)g_esrc[e] * DIM + lane * 4);
        acc.x += v.x; acc.y += v.y; acc.z += v.z; acc.w += v.w;
    }
    float sc = (s1 > s0) ? 1.f / (float)(s1 - s0) : 0.f;
    float2 f01 = make_float2(acc.x * sc, acc.y * sc);
    float2 f23 = make_float2(acc.z * sc, acc.w * sc);
    size_t base = (size_t)w * 64 + lane * 2;
    *(uint2*)(g_A1h + base) = make_uint2(split_pack_hi(f01), split_pack_hi(f23));
    *(uint2*)(g_A1l + base) = make_uint2(split_pack_lo(f01), split_pack_lo(f23));
}
__global__ __launch_bounds__(256) void k_gather2() {
    int w = (int)((blockIdx.x * 256u + threadIdx.x) >> 5);
    if (w >= NSEG2) return;
    int lane = threadIdx.x & 31;
    int s0 = g_off[w], s1 = g_off[w + 1];
    float4 acc = make_float4(0.f, 0.f, 0.f, 0.f);
    for (int e = s0; e < s1; e++) {
        const float4 v = *(const float4*)(g_x1 + (size_t)g_esrc[e] * DIM + lane * 4);
        acc.x += v.x; acc.y += v.y; acc.z += v.z; acc.w += v.w;
    }
    float sc = (s1 > s0) ? 1.f / (float)(s1 - s0) : 0.f;
    float2 f01 = make_float2(acc.x * sc, acc.y * sc);
    float2 f23 = make_float2(acc.z * sc, acc.w * sc);
    size_t base = (size_t)w * 64 + lane * 2;
    *(uint2*)(g_A2h + base) = make_uint2(split_pack_hi(f01), split_pack_hi(f23));
    *(uint2*)(g_A2l + base) = make_uint2(split_pack_lo(f01), split_pack_lo(f23));
}

// ---------------- pipelined HMMA GEMM core (K=32 chunks, 28 chunks) ----------------
// chunk cc (0..27): cc<24 -> agg[(grow*6 + cc/4)*64 + (cc&3)*16]; else root[grow*64 + (cc-24)*16]
#define STAGE_CHUNK(c_, s_, AGGH, AGGL, ROOTH, ROOTL, BTH, BTL, NLIM)                         \
    do {                                                                                      \
        int cc = (c_);                                                                        \
        uint32_t sb0 = sbase + (uint32_t)((s_) * 4) * PTILE;                                  \
        _Pragma("unroll")                                                                     \
        for (int k = 0; k < 2; k++) {                                                         \
            int idx = tid + k * 256;                                                          \
            int row = idx >> 2, c16 = idx & 3;                                                \
            int grow = m0 + row; if (grow >= (NLIM)) grow = (NLIM) - 1;                       \
            const uint32_t *srch, *srcl;                                                      \
            if (cc < 24) {                                                                    \
                size_t sgb = ((size_t)grow * 6 + (cc >> 2)) * 64 + (cc & 3) * 16;             \
                srch = (AGGH) + sgb; srcl = (AGGL) + sgb;                                     \
            } else {                                                                          \
                size_t sgb = (size_t)grow * 64 + (cc - 24) * 16;                              \
                srch = (ROOTH) + sgb; srcl = (ROOTL) + sgb;                                   \
            }                                                                                 \
            uint32_t so = (uint32_t)(row * 80 + c16 * 16);                                    \
            cpa16(sb0 + 0 * PTILE + so, srch + c16 * 4);                                      \
            cpa16(sb0 + 1 * PTILE + so, srcl + c16 * 4);                                      \
            const uint32_t* bh = (BTH) + (size_t)row * 448 + cc * 16;                         \
            const uint32_t* bl = (BTL) + (size_t)row * 448 + cc * 16;                         \
            cpa16(sb0 + 2 * PTILE + so, bh + c16 * 4);                                        \
            cpa16(sb0 + 3 * PTILE + so, bl + c16 * 4);                                        \
        }                                                                                     \
        CP_COMMIT();                                                                          \
    } while (0)

#define MMA_CHUNK(s_)                                                                         \
    do {                                                                                      \
        uint32_t sb0 = sbase + (uint32_t)((s_) * 4) * PTILE;                                  \
        _Pragma("unroll")                                                                     \
        for (int kk = 0; kk < 2; kk++) {                                                      \
            uint32_t ah[2][4], al[2][4], bh[4][4], bl[4][4];                                  \
            _Pragma("unroll")                                                                 \
            for (int mt = 0; mt < 2; mt++) {                                                  \
                uint32_t off = (uint32_t)((wm * 32 + mt * 16 + lrow) * 80 + kk * 32 + lk * 16); \
                ldm4(ah[mt], sb0 + 0 * PTILE + off);                                          \
                ldm4(al[mt], sb0 + 1 * PTILE + off);                                          \
            }                                                                                 \
            _Pragma("unroll")                                                                 \
            for (int nt = 0; nt < 4; nt++) {                                                  \
                uint32_t off = (uint32_t)((wn * 64 + nt * 16 + lrow) * 80 + kk * 32 + lk * 16); \
                ldm4(bh[nt], sb0 + 2 * PTILE + off);                                          \
                ldm4(bl[nt], sb0 + 3 * PTILE + off);                                          \
            }                                                                                 \
            _Pragma("unroll")                                                                 \
            for (int mt = 0; mt < 2; mt++)                                                    \
                _Pragma("unroll")                                                             \
                for (int nt = 0; nt < 4; nt++) {                                              \
                    mma_bf16(acc[mt][2 * nt],     ah[mt], bh[nt][0], bh[nt][2]);              \
                    mma_bf16(acc[mt][2 * nt + 1], ah[mt], bh[nt][1], bh[nt][3]);              \
                    mma_bf16(acc[mt][2 * nt],     al[mt], bh[nt][0], bh[nt][2]);              \
                    mma_bf16(acc[mt][2 * nt + 1], al[mt], bh[nt][1], bh[nt][3]);              \
                    mma_bf16(acc[mt][2 * nt],     ah[mt], bl[nt][0], bl[nt][2]);              \
                    mma_bf16(acc[mt][2 * nt + 1], ah[mt], bl[nt][1], bl[nt][3]);              \
                }                                                                             \
        }                                                                                     \
    } while (0)

// GEMM1: x1 = relu([agg1 | emb] @ B1' + bias1); writes fp32 x1 + split X1
__global__ __launch_bounds__(256, 2) void k_gemm1_p(const float* __restrict__ bias1) {
    extern __shared__ char sm[];
    const uint32_t sbase = smem_u32(sm);
    const int tid = threadIdx.x, lane = tid & 31, wid = tid >> 5;
    const int wm = wid & 3, wn = wid >> 2;
    const int lrow = lane & 15, lk = lane >> 4;
    const int m0 = blockIdx.x * 128;

    float acc[2][8][4];
    #pragma unroll
    for (int i = 0; i < 2; i++)
        #pragma unroll
        for (int j = 0; j < 8; j++)
            #pragma unroll
            for (int c = 0; c < 4; c++) acc[i][j][c] = 0.f;

    STAGE_CHUNK(0, 0, g_A1h, g_A1l, g_Eh, g_El, g_BT1h, g_BT1l, N_NODES);
    for (int c = 0; c < 28; c++) {
        int s = c & 1;
        if (c < 27) {
            STAGE_CHUNK(c + 1, s ^ 1, g_A1h, g_A1l, g_Eh, g_El, g_BT1h, g_BT1l, N_NODES);
            CP_WAIT(1);
        } else {
            CP_WAIT(0);
        }
        __syncthreads();
        MMA_CHUNK(s);
        __syncthreads();
    }

    const int g = lane >> 2, tc = lane & 3;
    #pragma unroll
    for (int mt = 0; mt < 2; mt++) {
        #pragma unroll
        for (int nb = 0; nb < 8; nb++) {
            int col = wn * 64 + nb * 8 + tc * 2;
            float b0 = bias1[col], b1 = bias1[col + 1];
            int pi = col >> 1;
            int r0 = m0 + wm * 32 + mt * 16 + g;
            if (r0 < N_NODES) {
                float2 v = make_float2(fmaxf(acc[mt][nb][0] + b0, 0.f), fmaxf(acc[mt][nb][1] + b1, 0.f));
                *(float2*)(g_x1 + (size_t)r0 * DIM + col) = v;
                g_X1h[(size_t)r0 * 64 + pi] = split_pack_hi(v);
                g_X1l[(size_t)r0 * 64 + pi] = split_pack_lo(v);
            }
            int r1 = r0 + 8;
            if (r1 < N_NODES) {
                float2 v = make_float2(fmaxf(acc[mt][nb][2] + b0, 0.f), fmaxf(acc[mt][nb][3] + b1, 0.f));
                *(float2*)(g_x1 + (size_t)r1 * DIM + col) = v;
                g_X1h[(size_t)r1 * 64 + pi] = split_pack_hi(v);
                g_X1l[(size_t)r1 * 64 + pi] = split_pack_lo(v);
            }
        }
    }
}

// GEMM2: x2 = [agg2 | x1] @ B2' + bias2
__global__ __launch_bounds__(256, 2) void k_gemm2_p(const float* __restrict__ bias2) {
    extern __shared__ char sm[];
    const uint32_t sbase = smem_u32(sm);
    const int tid = threadIdx.x, lane = tid & 31, wid = tid >> 5;
    const int wm = wid & 3, wn = wid >> 2;
    const int lrow = lane & 15, lk = lane >> 4;
    const int m0 = blockIdx.x * 128;

    float acc[2][8][4];
    #pragma unroll
    for (int i = 0; i < 2; i++)
        #pragma unroll
        for (int j = 0; j < 8; j++)
            #pragma unroll
            for (int c = 0; c < 4; c++) acc[i][j][c] = 0.f;

    STAGE_CHUNK(0, 0, g_A2h, g_A2l, g_X1h, g_X1l, g_BT2h, g_BT2l, NOUT2);
    for (int c = 0; c < 28; c++) {
        int s = c & 1;
        if (c < 27) {
            STAGE_CHUNK(c + 1, s ^ 1, g_A2h, g_A2l, g_X1h, g_X1l, g_BT2h, g_BT2l, NOUT2);
            CP_WAIT(1);
        } else {
            CP_WAIT(0);
        }
        __syncthreads();
        MMA_CHUNK(s);
        __syncthreads();
    }

    const int g = lane >> 2, tc = lane & 3;
    #pragma unroll
    for (int mt = 0; mt < 2; mt++) {
        #pragma unroll
        for (int nb = 0; nb < 8; nb++) {
            int col = wn * 64 + nb * 8 + tc * 2;
            float b0 = bias2[col], b1 = bias2[col + 1];
            int r0 = m0 + wm * 32 + mt * 16 + g;
            if (r0 < NOUT2)
                *(float2*)(g_x2 + (size_t)r0 * DIM + col) =
                    make_float2(acc[mt][nb][0] + b0, acc[mt][nb][1] + b1);
            int r1 = r0 + 8;
            if (r1 < NOUT2)
                *(float2*)(g_x2 + (size_t)r1 * DIM + col) =
                    make_float2(acc[mt][nb][2] + b0, acc[mt][nb][3] + b1);
        }
    }
}

// ---------------- scorer (HMMA, round-5 proven) ----------------
__global__ __launch_bounds__(256) void k_scorer_mma(const int* __restrict__ h_idx, const int* __restrict__ p_idx,
                                                    const float* __restrict__ sb1, const float* __restrict__ sw2,
                                                    const float* __restrict__ sb2, float* __restrict__ out) {
    extern __shared__ char sm[];
    uint32_t* Ah = (uint32_t*)sm;
    uint32_t* Al = (uint32_t*)(sm + TILE_BYTES);
    uint32_t* Bh = (uint32_t*)(sm + 2 * TILE_BYTES);
    uint32_t* Bl = (uint32_t*)(sm + 3 * TILE_BYTES);
    const uint32_t sAh = smem_u32(Ah), sAl = smem_u32(Al), sBh = smem_u32(Bh), sBl = smem_u32(Bl);
    const int tid = threadIdx.x, lane = tid & 31, wid = tid >> 5;
    const int wm = wid & 3, wn = wid >> 2;
    const int lrow = lane & 15, lk = lane >> 4;
    const int pair0 = blockIdx.x * 128;

    float acc[2][8][4];
    #pragma unroll
    for (int i = 0; i < 2; i++)
        #pragma unroll
        for (int j = 0; j < 8; j++)
            #pragma unroll
            for (int c = 0; c < 4; c++) acc[i][j][c] = 0.f;

    for (int c = 0; c < 4; c++) {
        for (int i = tid; i < 128 * 64; i += 256) {
            int row = i >> 6, k2 = i & 63;
            int pr = pair0 + row; if (pr >= NP) pr = NP - 1;
            float2 h = *(const float2*)(g_x2 + (size_t)h_idx[pr] * DIM + k2 * 2);
            float2 p = *(const float2*)(g_x2 + (size_t)(N_HERB + p_idx[pr]) * DIM + k2 * 2);
            float2 f;
            if (c == 0) f = h;
            else if (c == 1) f = p;
            else if (c == 2) f = make_float2(h.x * p.x, h.y * p.y);
            else f = make_float2(fabsf(h.x - p.x), fabsf(h.y - p.y));
            Ah[row * TSTR + k2] = split_pack_hi(f);
            Al[row * TSTR + k2] = split_pack_lo(f);
            Bh[row * TSTR + k2] = g_SW1h[(size_t)row * 256 + c * 64 + k2];
            Bl[row * TSTR + k2] = g_SW1l[(size_t)row * 256 + c * 64 + k2];
        }
        __syncthreads();
        #pragma unroll
        for (int kk8 = 0; kk8 < 8; kk8++) {
            uint32_t ah[2][4], al[2][4], bh[4][4], bl[4][4];
            #pragma unroll
            for (int mt = 0; mt < 2; mt++) {
                uint32_t off = (uint32_t)((wm * 32 + mt * 16 + lrow) * 272 + kk8 * 32 + lk * 16);
                ldm4(ah[mt], sAh + off);
                ldm4(al[mt], sAl + off);
            }
            #pragma unroll
            for (int nt = 0; nt < 4; nt++) {
                uint32_t off = (uint32_t)((wn * 64 + nt * 16 + lrow) * 272 + kk8 * 32 + lk * 16);
                ldm4(bh[nt], sBh + off);
                ldm4(bl[nt], sBl + off);
            }
            #pragma unroll
            for (int mt = 0; mt < 2; mt++)
                #pragma unroll
                for (int nt = 0; nt < 4; nt++) {
                    mma_bf16(acc[mt][2 * nt],     ah[mt], bh[nt][0], bh[nt][2]);
                    mma_bf16(acc[mt][2 * nt + 1], ah[mt], bh[nt][1], bh[nt][3]);
                    mma_bf16(acc[mt][2 * nt],     al[mt], bh[nt][0], bh[nt][2]);
                    mma_bf16(acc[mt][2 * nt + 1], al[mt], bh[nt][1], bh[nt][3]);
                    mma_bf16(acc[mt][2 * nt],     ah[mt], bl[nt][0], bl[nt][2]);
                    mma_bf16(acc[mt][2 * nt + 1], ah[mt], bl[nt][1], bl[nt][3]);
                }
        }
        __syncthreads();
    }

    __syncthreads();
    float* s_part = (float*)sm;              // [128][2]
    const int g = lane >> 2, tc = lane & 3;
    #pragma unroll
    for (int mt = 0; mt < 2; mt++) {
        float s0 = 0.f, s1 = 0.f;
        #pragma unroll
        for (int nb = 0; nb < 8; nb++) {
            int col = wn * 64 + nb * 8 + tc * 2;
            float w0 = sw2[col], w1 = sw2[col + 1];
            float bb0 = sb1[col], bb1 = sb1[col + 1];
            s0 += fmaxf(acc[mt][nb][0] + bb0, 0.f) * w0 + fmaxf(acc[mt][nb][1] + bb1, 0.f) * w1;
            s1 += fmaxf(acc[mt][nb][2] + bb0, 0.f) * w0 + fmaxf(acc[mt][nb][3] + bb1, 0.f) * w1;
        }
        s0 += __shfl_xor_sync(0xffffffff, s0, 1); s0 += __shfl_xor_sync(0xffffffff, s0, 2);
        s1 += __shfl_xor_sync(0xffffffff, s1, 1); s1 += __shfl_xor_sync(0xffffffff, s1, 2);
        if (tc == 0) {
            int r0 = wm * 32 + mt * 16 + g;
            s_part[r0 * 2 + wn] = s0;
            s_part[(r0 + 8) * 2 + wn] = s1;
        }
    }
    __syncthreads();
    if (tid < 128) {
        int pr = pair0 + tid;
        if (pr < NP) out[pr] = s_part[tid * 2] + s_part[tid * 2 + 1] + sb2[0];
    }
}

// ---------------- launch ----------------
extern "C" void kernel_launch(void* const* d_in, const int* in_sizes, int n_in,
                              void* d_out, int out_size) {
    const int*   edge_index = (const int*)d_in[0];
    const int*   edge_type  = (const int*)d_in[1];
    const int*   h_idx      = (const int*)d_in[2];
    const int*   p_idx      = (const int*)d_in[3];
    const float* node_emb   = (const float*)d_in[4];
    const float* basis1 = (const float*)d_in[5];
    const float* comp1  = (const float*)d_in[6];
    const float* root1  = (const float*)d_in[7];
    const float* bias1  = (const float*)d_in[8];
    const float* basis2 = (const float*)d_in[9];
    const float* comp2  = (const float*)d_in[10];
    const float* root2  = (const float*)d_in[11];
    const float* bias2  = (const float*)d_in[12];
    const float* sw1 = (const float*)d_in[13];
    const float* sb1 = (const float*)d_in[14];
    const float* sw2 = (const float*)d_in[15];
    const float* sb2 = (const float*)d_in[16];
    float* out = (float*)d_out;

    cudaFuncSetAttribute(k_gemm1_p, cudaFuncAttributeMaxDynamicSharedMemorySize, PSMEM);
    cudaFuncSetAttribute(k_gemm2_p, cudaFuncAttributeMaxDynamicSharedMemorySize, PSMEM);
    cudaFuncSetAttribute(k_scorer_mma, cudaFuncAttributeMaxDynamicSharedMemorySize, 4 * TILE_BYTES);

    k_build_w1<<<(128 * 448 + 255) / 256, 256>>>(basis1, comp1, root1);
    k_build_w2<<<(128 * 448 + 255) / 256, 256>>>(basis2, comp2, root2);
    k_build_sw1t<<<(128 * 256 + 255) / 256, 256>>>(sw1);
    k_build_emb<<<(N_NODES * 64 + 255) / 256, 256>>>(node_emb);

    k_zero_cnt<<<(NSEG1 + 255) / 256, 256>>>();
    k_count<<<(NE + 255) / 256, 256>>>(edge_index, edge_type);
    k_scan_a<<<NBLK, SCAN_BLK>>>();
    k_scan_b<<<1, 512>>>();
    k_scan_c<<<NBLK, SCAN_BLK>>>();
    k_fill<<<(NE + 255) / 256, 256>>>(edge_index, edge_type);

    k_gather1<<<(NSEG1 * 32 + 255) / 256, 256>>>(node_emb);
    k_gemm1_p<<<(N_NODES + 127) / 128, 256, PSMEM>>>(bias1);

    k_gather2<<<(NSEG2 * 32 + 255) / 256, 256>>>();
    k_gemm2_p<<<(NOUT2 + 127) / 128, 256, PSMEM>>>(bias2);

    k_scorer_mma<<<(NP + 127) / 128, 256, 4 * TILE_BYTES>>>(h_idx, p_idx, sb1, sw2, sb2, out);
}